// round 1
// baseline (speedup 1.0000x reference)
#include <cuda_runtime.h>
#include <cstdint>

#define Nn 512
#define Cc 128
#define PP (Nn*Nn)   // 262144 positions

// Scratch (device globals — no allocation allowed in kernel_launch)
__device__ float g_a[(size_t)Cc*PP];     // [c][i][k]  channel-major A operand
__device__ float g_b[(size_t)Cc*PP];     // [c][j][k]  channel-major B operand
__device__ float g_gate[(size_t)PP*Cc];  // [p][c]     sigmoid output gate
__device__ float g_tri[(size_t)Cc*PP];   // [c][i][j]  triangle result

__device__ __forceinline__ float sigmoidf_(float v) {
    return 1.f / (1.f + __expf(-v));
}

// ---------------------------------------------------------------------------
// K1: per-position LayerNorm + three fused projections.
//   xn = LN(x);  a,b = (xn@p_in_w^T) * sigmoid(xn@g_in_w^T)  (split 128/128)
//   gate = sigmoid(xn@g_out_w^T)
// Block: 64 positions, 256 threads. a/b written channel-major via smem staging.
// ---------------------------------------------------------------------------
__global__ __launch_bounds__(256) void k1_ln_proj(
    const float* __restrict__ x,
    const float* __restrict__ niw, const float* __restrict__ nib,
    const float* __restrict__ giw, const float* __restrict__ piw,
    const float* __restrict__ gow)
{
    extern __shared__ float sm[];
    float* xn = sm;                 // [128 k][68]  (64 pos, pad 68)
    float* Wg = xn + 128*68;        // [128 k][68]  (64 d,  pad 68)
    float* Wp = Wg + 128*68;
    float* ob = Wp + 128*68;        // [64 d][65]   staging for transposed write

    const int tid = threadIdx.x;
    const int p0 = blockIdx.x * 64;

    // --- LayerNorm: 4 threads per position, 32 channels each ---
    {
        int pos = tid >> 2, sub = tid & 3;
        const float* xr = x + (size_t)(p0 + pos) * Cc + sub * 32;
        float s = 0.f, sq = 0.f;
        #pragma unroll
        for (int t = 0; t < 8; ++t) {
            float4 f = *(const float4*)(xr + t*4);
            s  += f.x + f.y + f.z + f.w;
            sq += f.x*f.x + f.y*f.y + f.z*f.z + f.w*f.w;
        }
        s  += __shfl_xor_sync(0xffffffffu, s, 1);
        s  += __shfl_xor_sync(0xffffffffu, s, 2);
        sq += __shfl_xor_sync(0xffffffffu, sq, 1);
        sq += __shfl_xor_sync(0xffffffffu, sq, 2);
        float mu   = s * (1.f/128.f);
        float var  = sq * (1.f/128.f) - mu*mu;
        float rstd = rsqrtf(var + 1e-5f);
        #pragma unroll
        for (int t = 0; t < 8; ++t) {
            float4 f = *(const float4*)(xr + t*4);
            int c = sub*32 + t*4;
            xn[(c+0)*68 + pos] = (f.x - mu)*rstd*niw[c+0] + nib[c+0];
            xn[(c+1)*68 + pos] = (f.y - mu)*rstd*niw[c+1] + nib[c+1];
            xn[(c+2)*68 + pos] = (f.z - mu)*rstd*niw[c+2] + nib[c+2];
            xn[(c+3)*68 + pos] = (f.w - mu)*rstd*niw[c+3] + nib[c+3];
        }
    }
    __syncthreads();

    const int tx = tid & 15, ty = tid >> 4;   // tx -> d (4tx), ty -> pos (4ty)

    // --- 4 dual tiles: g_in & p_in share d range [64t, 64t+64) ---
    for (int t = 0; t < 4; ++t) {
        const float* gsrc = giw + (size_t)t*64*Cc;
        const float* psrc = piw + (size_t)t*64*Cc;
        for (int idx = tid; idx < 64*128; idx += 256) {
            int d = idx >> 7, k = idx & 127;
            Wg[k*68 + d] = gsrc[idx];
            Wp[k*68 + d] = psrc[idx];
        }
        __syncthreads();
        float ag[4][4] = {}, ap[4][4] = {};
        #pragma unroll 8
        for (int k = 0; k < 128; ++k) {
            float4 xv = *(const float4*)&xn[k*68 + 4*ty];
            float4 wg = *(const float4*)&Wg[k*68 + 4*tx];
            float4 wp = *(const float4*)&Wp[k*68 + 4*tx];
            float xa[4] = {xv.x,xv.y,xv.z,xv.w};
            float ga[4] = {wg.x,wg.y,wg.z,wg.w};
            float pa[4] = {wp.x,wp.y,wp.z,wp.w};
            #pragma unroll
            for (int v = 0; v < 4; ++v)
                #pragma unroll
                for (int u = 0; u < 4; ++u) {
                    ag[v][u] += xa[v]*ga[u];
                    ap[v][u] += xa[v]*pa[u];
                }
        }
        // pg = p * sigmoid(g), stage transposed [d][pos]
        #pragma unroll
        for (int v = 0; v < 4; ++v)
            #pragma unroll
            for (int u = 0; u < 4; ++u)
                ob[(4*tx+u)*65 + 4*ty+v] = ap[v][u] * sigmoidf_(ag[v][u]);
        __syncthreads();
        {
            float* dst = (t < 2) ? (g_a + (size_t)(t*64)*PP)
                                 : (g_b + (size_t)((t-2)*64)*PP);
            int pc = tid & 63, dr = tid >> 6;
            #pragma unroll
            for (int r = 0; r < 16; ++r) {
                int d = r*4 + dr;
                dst[(size_t)d*PP + p0 + pc] = ob[d*65 + pc];
            }
        }
        __syncthreads();
    }

    // --- 2 tiles: g_out -> gate (stored [p][c]) ---
    for (int t = 0; t < 2; ++t) {
        const float* gsrc = gow + (size_t)t*64*Cc;
        for (int idx = tid; idx < 64*128; idx += 256) {
            int d = idx >> 7, k = idx & 127;
            Wg[k*68 + d] = gsrc[idx];
        }
        __syncthreads();
        float ag[4][4] = {};
        #pragma unroll 8
        for (int k = 0; k < 128; ++k) {
            float4 xv = *(const float4*)&xn[k*68 + 4*ty];
            float4 wg = *(const float4*)&Wg[k*68 + 4*tx];
            float xa[4] = {xv.x,xv.y,xv.z,xv.w};
            float ga[4] = {wg.x,wg.y,wg.z,wg.w};
            #pragma unroll
            for (int v = 0; v < 4; ++v)
                #pragma unroll
                for (int u = 0; u < 4; ++u)
                    ag[v][u] += xa[v]*ga[u];
        }
        #pragma unroll
        for (int v = 0; v < 4; ++v) {
            size_t p = (size_t)(p0 + 4*ty + v);
            float4 o;
            o.x = sigmoidf_(ag[v][0]); o.y = sigmoidf_(ag[v][1]);
            o.z = sigmoidf_(ag[v][2]); o.w = sigmoidf_(ag[v][3]);
            *(float4*)&g_gate[p*Cc + t*64 + 4*tx] = o;
        }
        __syncthreads();
    }
}

// ---------------------------------------------------------------------------
// K2: per-channel triangle GEMM: tri_c = A_c @ B_c^T  (512x512x512, 128 ch)
// 128x128 tile, ktile 32, 256 threads, 8x8 microtile as 2x2 strips of 4
// (conflict-free float4 smem reads). grid = (4, 4, 128).
// ---------------------------------------------------------------------------
__global__ __launch_bounds__(256) void k2_trimul()
{
    __shared__ float As[32*132];   // [k][i] padded
    __shared__ float Bs[32*132];   // [k][j] padded
    const int c = blockIdx.z;
    const float* A = g_a + (size_t)c*PP;
    const float* B = g_b + (size_t)c*PP;
    float* Cm = g_tri + (size_t)c*PP;
    const int i0 = blockIdx.y*128, j0 = blockIdx.x*128;
    const int tid  = threadIdx.x;
    const int lane = tid & 31, wr = tid >> 5;
    const int tx = tid & 15, ty = tid >> 4;

    float acc[2][2][4][4] = {};

    for (int kk = 0; kk < 512; kk += 32) {
        __syncthreads();
        #pragma unroll
        for (int r = wr; r < 128; r += 8) {
            As[lane*132 + r] = A[(size_t)(i0 + r)*Nn + kk + lane];
            Bs[lane*132 + r] = B[(size_t)(j0 + r)*Nn + kk + lane];
        }
        __syncthreads();
        #pragma unroll 8
        for (int k = 0; k < 32; ++k) {
            float4 a0 = *(const float4*)&As[k*132 + 4*ty];
            float4 a1 = *(const float4*)&As[k*132 + 64 + 4*ty];
            float4 b0 = *(const float4*)&Bs[k*132 + 4*tx];
            float4 b1 = *(const float4*)&Bs[k*132 + 64 + 4*tx];
            float av[2][4] = {{a0.x,a0.y,a0.z,a0.w},{a1.x,a1.y,a1.z,a1.w}};
            float bv[2][4] = {{b0.x,b0.y,b0.z,b0.w},{b1.x,b1.y,b1.z,b1.w}};
            #pragma unroll
            for (int ia = 0; ia < 2; ++ia)
                #pragma unroll
                for (int jb = 0; jb < 2; ++jb)
                    #pragma unroll
                    for (int v = 0; v < 4; ++v)
                        #pragma unroll
                        for (int u = 0; u < 4; ++u)
                            acc[ia][jb][v][u] += av[ia][v]*bv[jb][u];
        }
    }
    #pragma unroll
    for (int ia = 0; ia < 2; ++ia)
        #pragma unroll
        for (int v = 0; v < 4; ++v) {
            int i = i0 + ia*64 + 4*ty + v;
            #pragma unroll
            for (int jb = 0; jb < 2; ++jb) {
                float4 o = {acc[ia][jb][v][0], acc[ia][jb][v][1],
                            acc[ia][jb][v][2], acc[ia][jb][v][3]};
                *(float4*)&Cm[(size_t)i*Nn + j0 + jb*64 + 4*tx] = o;
            }
        }
}

// ---------------------------------------------------------------------------
// K3: out = (LN_c(tri) @ p_out_w^T) * gate
// Block: one i row, 32 j columns, 256 threads. Transposes tri (c-major ->
// position-major) through smem, LN over c, then 32x128 projection.
// grid = (16, 512).
// ---------------------------------------------------------------------------
__global__ __launch_bounds__(256) void k3_out(
    const float* __restrict__ now, const float* __restrict__ nob,
    const float* __restrict__ poww, float* __restrict__ out)
{
    extern __shared__ float sm[];
    float* Ws = sm;             // [c][d] 128x132 (transposed p_out_w)
    float* ts = Ws + 128*132;   // [c][j] 128x36
    const int tid = threadIdx.x;
    const int i = blockIdx.y, j0 = blockIdx.x*32;

    for (int idx = tid; idx < 128*128; idx += 256) {
        int d = idx >> 7, c = idx & 127;
        Ws[c*132 + d] = poww[idx];
    }
    for (int idx = tid; idx < 128*32; idx += 256) {
        int c = idx >> 5, j = idx & 31;
        ts[c*36 + j] = g_tri[(size_t)c*PP + (size_t)i*Nn + j0 + j];
    }
    __syncthreads();

    // LayerNorm over c: 8 lanes per position
    {
        int jl = tid >> 3, sub = tid & 7;
        float s = 0.f, sq = 0.f;
        #pragma unroll
        for (int t = 0; t < 16; ++t) {
            float v = ts[(sub + 8*t)*36 + jl];
            s += v; sq += v*v;
        }
        s  += __shfl_xor_sync(0xffffffffu, s, 1);
        s  += __shfl_xor_sync(0xffffffffu, s, 2);
        s  += __shfl_xor_sync(0xffffffffu, s, 4);
        sq += __shfl_xor_sync(0xffffffffu, sq, 1);
        sq += __shfl_xor_sync(0xffffffffu, sq, 2);
        sq += __shfl_xor_sync(0xffffffffu, sq, 4);
        float mu   = s*(1.f/128.f);
        float rstd = rsqrtf(fmaxf(sq*(1.f/128.f) - mu*mu, 0.f) + 1e-5f);
        #pragma unroll
        for (int t = 0; t < 16; ++t) {
            int c = sub + 8*t;
            ts[c*36 + jl] = (ts[c*36 + jl] - mu)*rstd*now[c] + nob[c];
        }
    }
    __syncthreads();

    const int tx = tid & 31, ty = tid >> 5;   // d = 4tx (0..127), j = 4ty (0..31)
    float acc[4][4] = {};
    #pragma unroll 8
    for (int c = 0; c < 128; ++c) {
        float4 L  = *(const float4*)&ts[c*36 + 4*ty];
        float4 W4 = *(const float4*)&Ws[c*132 + 4*tx];
        float la[4] = {L.x,L.y,L.z,L.w};
        float wa[4] = {W4.x,W4.y,W4.z,W4.w};
        #pragma unroll
        for (int v = 0; v < 4; ++v)
            #pragma unroll
            for (int u = 0; u < 4; ++u)
                acc[v][u] += la[v]*wa[u];
    }
    #pragma unroll
    for (int v = 0; v < 4; ++v) {
        size_t p   = (size_t)i*Nn + j0 + 4*ty + v;
        size_t off = p*Cc + 4*tx;
        float4 g4 = *(const float4*)&g_gate[off];
        float4 o = { acc[v][0]*g4.x, acc[v][1]*g4.y,
                     acc[v][2]*g4.z, acc[v][3]*g4.w };
        *(float4*)&out[off] = o;
    }
}

// ---------------------------------------------------------------------------
extern "C" void kernel_launch(void* const* d_in, const int* in_sizes, int n_in,
                              void* d_out, int out_size)
{
    const float* x    = (const float*)d_in[0];
    const float* niw  = (const float*)d_in[1];
    const float* nib  = (const float*)d_in[2];
    const float* giw  = (const float*)d_in[3];
    const float* piw  = (const float*)d_in[4];
    const float* gow  = (const float*)d_in[5];
    const float* now  = (const float*)d_in[6];
    const float* nob  = (const float*)d_in[7];
    const float* poww = (const float*)d_in[8];
    float* out = (float*)d_out;

    const int k1_smem = (3*128*68 + 64*65) * 4;     // 121088 B
    const int k3_smem = (128*132 + 128*36) * 4;     //  86016 B
    cudaFuncSetAttribute(k1_ln_proj, cudaFuncAttributeMaxDynamicSharedMemorySize, k1_smem);
    cudaFuncSetAttribute(k3_out,     cudaFuncAttributeMaxDynamicSharedMemorySize, k3_smem);

    k1_ln_proj<<<PP/64, 256, k1_smem>>>(x, niw, nib, giw, piw, gow);
    k2_trimul<<<dim3(4, 4, 128), 256>>>();
    k3_out<<<dim3(Nn/32, Nn), 256, k3_smem>>>(now, nob, poww, out);
}

// round 4
// speedup vs baseline: 1.6633x; 1.6633x over previous
#include <cuda_runtime.h>
#include <cstdint>

#define Nn 512
#define Cc 128
#define PP (Nn*Nn)   // 262144 positions

// Scratch (device globals — no allocation allowed in kernel_launch)
__device__ float g_a[(size_t)Cc*PP];     // [c][i][k]  channel-major A operand
__device__ float g_b[(size_t)Cc*PP];     // [c][j][k]  channel-major B operand
__device__ float g_gate[(size_t)PP*Cc];  // [p][c]     sigmoid output gate
__device__ float g_tri[(size_t)Cc*PP];   // [c][i][j]  triangle result

__device__ __forceinline__ float sigmoidf_(float v) {
    return 1.f / (1.f + __expf(-v));
}

// ===================== mma.sync tf32 helpers (sm_80+, no 'a' features) =====
__device__ __forceinline__ uint32_t smem_u32(const void* p) {
    uint32_t a;
    asm("{ .reg .u64 t; cvta.to.shared.u64 t, %1; cvt.u32.u64 %0, t; }"
        : "=r"(a) : "l"(p));
    return a;
}
__device__ __forceinline__ uint32_t cvt_tf32(float f) {
    uint32_t r;
    asm("cvt.rna.tf32.f32 %0, %1;" : "=r"(r) : "f"(f));
    return r;
}
__device__ __forceinline__ void split_tf32(float f, uint32_t& hi, uint32_t& lo) {
    hi = cvt_tf32(f);
    lo = cvt_tf32(f - __uint_as_float(hi));
}
__device__ __forceinline__ void mma_tf32(float* d, const uint32_t* a, const uint32_t* b) {
    asm volatile(
        "mma.sync.aligned.m16n8k8.row.col.f32.tf32.tf32.f32 "
        "{%0,%1,%2,%3}, {%4,%5,%6,%7}, {%8,%9}, {%0,%1,%2,%3};"
        : "+f"(d[0]), "+f"(d[1]), "+f"(d[2]), "+f"(d[3])
        : "r"(a[0]), "r"(a[1]), "r"(a[2]), "r"(a[3]), "r"(b[0]), "r"(b[1]));
}
__device__ __forceinline__ void cp16(uint32_t s, const void* g) {
    asm volatile("cp.async.cg.shared.global [%0], [%1], 16;" :: "r"(s), "l"(g));
}
#define CP_COMMIT() asm volatile("cp.async.commit_group;" ::: "memory")
#define CP_WAIT0()  asm volatile("cp.async.wait_group 0;" ::: "memory")

// ---------------------------------------------------------------------------
// K1: LN + 3 projections via tf32 mma with 3-term precision split.
// Block = 128 positions, 256 threads (8 warps: 4 pos-warps x 2 d-warps).
// xn smem [128 pos][132] fp32. Weight d-tiles of 64.
// ---------------------------------------------------------------------------
#define XS 132

__global__ __launch_bounds__(256) void k1_ln_proj(
    const float* __restrict__ x,
    const float* __restrict__ niw, const float* __restrict__ nib,
    const float* __restrict__ giw, const float* __restrict__ piw,
    const float* __restrict__ gow)
{
    extern __shared__ float sm[];
    float* xn = sm;            // [128][132]
    float* Wg = xn + 128*XS;   // [64][132]  (also reused as pg staging)
    float* Wp = Wg + 64*XS;    // [64][132]

    const int tid  = threadIdx.x;
    const int p0   = blockIdx.x * 128;
    const int lane = tid & 31, wid = tid >> 5;
    const int wm = wid & 3, wn = wid >> 2;   // pos-warp (32 rows), d-warp (32 cols)
    const int g4 = lane >> 2, t4 = lane & 3;

    // ---- LayerNorm: 2 threads per position, 64 channels each ----
    {
        int pos = tid >> 1, sub = tid & 1;
        const float* xr = x + (size_t)(p0 + pos) * Cc + sub * 64;
        float4 bufv[16];
        float s = 0.f, sq = 0.f;
        #pragma unroll
        for (int t = 0; t < 16; ++t) {
            bufv[t] = ((const float4*)xr)[t];
            s  += bufv[t].x + bufv[t].y + bufv[t].z + bufv[t].w;
            sq += bufv[t].x*bufv[t].x + bufv[t].y*bufv[t].y
                + bufv[t].z*bufv[t].z + bufv[t].w*bufv[t].w;
        }
        s  += __shfl_xor_sync(0xffffffffu, s, 1);
        sq += __shfl_xor_sync(0xffffffffu, sq, 1);
        float mu   = s * (1.f/128.f);
        float rstd = rsqrtf(sq * (1.f/128.f) - mu*mu + 1e-5f);
        #pragma unroll
        for (int t = 0; t < 16; ++t) {
            int cb = sub*64 + t*4;
            float4 w4 = *(const float4*)(niw + cb);
            float4 b4 = *(const float4*)(nib + cb);
            float4 o;
            o.x = (bufv[t].x - mu)*rstd*w4.x + b4.x;
            o.y = (bufv[t].y - mu)*rstd*w4.y + b4.y;
            o.z = (bufv[t].z - mu)*rstd*w4.z + b4.z;
            o.w = (bufv[t].w - mu)*rstd*w4.w + b4.w;
            *(float4*)&xn[pos*XS + cb] = o;
        }
    }
    __syncthreads();

    // ---- 4 d-tiles of 64: G = xn@g_in^T, P = xn@p_in^T, pg = P*sigmoid(G) ----
    for (int t = 0; t < 4; ++t) {
        const float* gsrc = giw + (size_t)t*64*Cc;
        const float* psrc = piw + (size_t)t*64*Cc;
        for (int q = tid; q < 2048; q += 256) {          // 64 rows x 32 float4
            int d = q >> 5, c4 = q & 31;
            *(float4*)&Wg[d*XS + c4*4] = *(const float4*)(gsrc + d*Cc + c4*4);
            *(float4*)&Wp[d*XS + c4*4] = *(const float4*)(psrc + d*Cc + c4*4);
        }
        __syncthreads();

        float accG[2][4][4] = {}, accP[2][4][4] = {};
        #pragma unroll 4
        for (int ks = 0; ks < 16; ++ks) {
            int kb = ks*8;
            uint32_t ah[2][4], al[2][4];
            #pragma unroll
            for (int mt = 0; mt < 2; ++mt) {
                int row = wm*32 + mt*16 + g4;
                split_tf32(xn[row*XS + kb + t4],         ah[mt][0], al[mt][0]);
                split_tf32(xn[(row+8)*XS + kb + t4],     ah[mt][1], al[mt][1]);
                split_tf32(xn[row*XS + kb + t4 + 4],     ah[mt][2], al[mt][2]);
                split_tf32(xn[(row+8)*XS + kb + t4 + 4], ah[mt][3], al[mt][3]);
            }
            uint32_t bgh[4][2], bgl[4][2], bph[4][2], bpl[4][2];
            #pragma unroll
            for (int nt = 0; nt < 4; ++nt) {
                int dn = wn*32 + nt*8 + g4;
                split_tf32(Wg[dn*XS + kb + t4],     bgh[nt][0], bgl[nt][0]);
                split_tf32(Wg[dn*XS + kb + t4 + 4], bgh[nt][1], bgl[nt][1]);
                split_tf32(Wp[dn*XS + kb + t4],     bph[nt][0], bpl[nt][0]);
                split_tf32(Wp[dn*XS + kb + t4 + 4], bph[nt][1], bpl[nt][1]);
            }
            #pragma unroll
            for (int mt = 0; mt < 2; ++mt)
                #pragma unroll
                for (int nt = 0; nt < 4; ++nt) {
                    mma_tf32(accG[mt][nt], ah[mt], bgh[nt]);
                    mma_tf32(accG[mt][nt], ah[mt], bgl[nt]);
                    mma_tf32(accG[mt][nt], al[mt], bgh[nt]);
                    mma_tf32(accP[mt][nt], ah[mt], bph[nt]);
                    mma_tf32(accP[mt][nt], ah[mt], bpl[nt]);
                    mma_tf32(accP[mt][nt], al[mt], bph[nt]);
                }
        }
        __syncthreads();     // everyone done reading Wg/Wp

        // pg = P * sigmoid(G), stage transposed [d][pos] into Wg
        float* ob = Wg;
        #pragma unroll
        for (int mt = 0; mt < 2; ++mt)
            #pragma unroll
            for (int nt = 0; nt < 4; ++nt) {
                int row = wm*32 + mt*16 + g4;
                int col = wn*32 + nt*8 + 2*t4;
                ob[col*XS + row]         = accP[mt][nt][0]*sigmoidf_(accG[mt][nt][0]);
                ob[(col+1)*XS + row]     = accP[mt][nt][1]*sigmoidf_(accG[mt][nt][1]);
                ob[col*XS + row + 8]     = accP[mt][nt][2]*sigmoidf_(accG[mt][nt][2]);
                ob[(col+1)*XS + row + 8] = accP[mt][nt][3]*sigmoidf_(accG[mt][nt][3]);
            }
        __syncthreads();

        float* dst = ((t < 2) ? g_a : g_b) + (size_t)((t & 1)*64)*PP + p0;
        for (int q = tid; q < 2048; q += 256) {          // 64 d x 32 f4
            int d = q >> 5, p4 = q & 31;
            *(float4*)(dst + (size_t)d*PP + p4*4) = *(float4*)&ob[d*XS + p4*4];
        }
        __syncthreads();
    }

    // ---- 2 gate tiles (1-term tf32; sigmoid makes rounding negligible) ----
    for (int t = 0; t < 2; ++t) {
        const float* gsrc = gow + (size_t)t*64*Cc;
        for (int q = tid; q < 2048; q += 256) {          // 64 rows x 32 float4
            int d = q >> 5, c4 = q & 31;
            *(float4*)&Wg[d*XS + c4*4] = *(const float4*)(gsrc + d*Cc + c4*4);
        }
        __syncthreads();

        float accG[2][4][4] = {};
        #pragma unroll 4
        for (int ks = 0; ks < 16; ++ks) {
            int kb = ks*8;
            uint32_t af[2][4];
            #pragma unroll
            for (int mt = 0; mt < 2; ++mt) {
                int row = wm*32 + mt*16 + g4;
                af[mt][0] = cvt_tf32(xn[row*XS + kb + t4]);
                af[mt][1] = cvt_tf32(xn[(row+8)*XS + kb + t4]);
                af[mt][2] = cvt_tf32(xn[row*XS + kb + t4 + 4]);
                af[mt][3] = cvt_tf32(xn[(row+8)*XS + kb + t4 + 4]);
            }
            uint32_t bf[4][2];
            #pragma unroll
            for (int nt = 0; nt < 4; ++nt) {
                int dn = wn*32 + nt*8 + g4;
                bf[nt][0] = cvt_tf32(Wg[dn*XS + kb + t4]);
                bf[nt][1] = cvt_tf32(Wg[dn*XS + kb + t4 + 4]);
            }
            #pragma unroll
            for (int mt = 0; mt < 2; ++mt)
                #pragma unroll
                for (int nt = 0; nt < 4; ++nt)
                    mma_tf32(accG[mt][nt], af[mt], bf[nt]);
        }
        #pragma unroll
        for (int mt = 0; mt < 2; ++mt)
            #pragma unroll
            for (int nt = 0; nt < 4; ++nt) {
                int row = wm*32 + mt*16 + g4;
                int col = t*64 + wn*32 + nt*8 + 2*t4;
                float2 o0 = { sigmoidf_(accG[mt][nt][0]), sigmoidf_(accG[mt][nt][1]) };
                float2 o1 = { sigmoidf_(accG[mt][nt][2]), sigmoidf_(accG[mt][nt][3]) };
                *(float2*)(g_gate + (size_t)(p0+row)*Cc + col)   = o0;
                *(float2*)(g_gate + (size_t)(p0+row+8)*Cc + col) = o1;
            }
        __syncthreads();
    }
}

// ---------------------------------------------------------------------------
// K2: per-channel tri_c = A_c @ B_c^T via plain tf32 mma. CTA tile 128x128,
// k-chunk 32, cp.async double buffer. grid = (4, 4, 128), 256 threads.
// ---------------------------------------------------------------------------
#define KS2 36
#define K2_BUF (128*KS2)

__global__ __launch_bounds__(256) void k2_trimul_tc()
{
    extern __shared__ float sm2[];
    float* As = sm2;               // [2][128][36]
    float* Bs = sm2 + 2*K2_BUF;    // [2][128][36]

    const int tid = threadIdx.x, lane = tid & 31, wid = tid >> 5;
    const int wm = wid & 3, wn = wid >> 2;   // i-warp (32), j-warp (64)
    const int g4 = lane >> 2, t4 = lane & 3;
    const int c = blockIdx.z, i0 = blockIdx.y*128, j0 = blockIdx.x*128;
    const float* Ag = g_a + (size_t)c*PP + (size_t)i0*Nn;
    const float* Bg = g_b + (size_t)c*PP + (size_t)j0*Nn;
    const uint32_t sA = smem_u32(As), sB = smem_u32(Bs);

    const int r_ld  = tid >> 3;          // 0..31 (x4 rows per thread via +32)
    const int c4_ld = tid & 7;

    float acc[2][8][4] = {};

    // prologue: chunk 0 -> buf 0
    #pragma unroll
    for (int q = 0; q < 4; ++q) {
        int r = r_ld + q*32;
        cp16(sA + (uint32_t)(r*KS2 + c4_ld*4)*4, Ag + (size_t)r*Nn + c4_ld*4);
        cp16(sB + (uint32_t)(r*KS2 + c4_ld*4)*4, Bg + (size_t)r*Nn + c4_ld*4);
    }
    CP_COMMIT();

    for (int kt = 0; kt < 16; ++kt) {
        const int buf = kt & 1;
        CP_WAIT0();
        __syncthreads();
        if (kt < 15) {
            const int kk = (kt+1)*32;
            const uint32_t off = (uint32_t)((buf^1)*K2_BUF)*4;
            #pragma unroll
            for (int q = 0; q < 4; ++q) {
                int r = r_ld + q*32;
                cp16(sA + off + (uint32_t)(r*KS2 + c4_ld*4)*4, Ag + (size_t)r*Nn + kk + c4_ld*4);
                cp16(sB + off + (uint32_t)(r*KS2 + c4_ld*4)*4, Bg + (size_t)r*Nn + kk + c4_ld*4);
            }
            CP_COMMIT();
        }
        const float* A = As + buf*K2_BUF;
        const float* B = Bs + buf*K2_BUF;
        #pragma unroll
        for (int ks = 0; ks < 4; ++ks) {
            int kb = ks*8;
            uint32_t af[2][4];
            #pragma unroll
            for (int mt = 0; mt < 2; ++mt) {
                int row = wm*32 + mt*16 + g4;
                af[mt][0] = cvt_tf32(A[row*KS2 + kb + t4]);
                af[mt][1] = cvt_tf32(A[(row+8)*KS2 + kb + t4]);
                af[mt][2] = cvt_tf32(A[row*KS2 + kb + t4 + 4]);
                af[mt][3] = cvt_tf32(A[(row+8)*KS2 + kb + t4 + 4]);
            }
            uint32_t bf[8][2];
            #pragma unroll
            for (int nt = 0; nt < 8; ++nt) {
                int nr = wn*64 + nt*8 + g4;
                bf[nt][0] = cvt_tf32(B[nr*KS2 + kb + t4]);
                bf[nt][1] = cvt_tf32(B[nr*KS2 + kb + t4 + 4]);
            }
            #pragma unroll
            for (int mt = 0; mt < 2; ++mt)
                #pragma unroll
                for (int nt = 0; nt < 8; ++nt)
                    mma_tf32(acc[mt][nt], af[mt], bf[nt]);
        }
        __syncthreads();
    }

    float* Cm = g_tri + (size_t)c*PP;
    #pragma unroll
    for (int mt = 0; mt < 2; ++mt)
        #pragma unroll
        for (int nt = 0; nt < 8; ++nt) {
            int row = i0 + wm*32 + mt*16 + g4;
            int col = j0 + wn*64 + nt*8 + 2*t4;
            float2 o0 = { acc[mt][nt][0], acc[mt][nt][1] };
            float2 o1 = { acc[mt][nt][2], acc[mt][nt][3] };
            *(float2*)(Cm + (size_t)row*Nn + col)     = o0;
            *(float2*)(Cm + (size_t)(row+8)*Nn + col) = o1;
        }
}

// ---------------------------------------------------------------------------
// K3: out = (LN_c(tri) @ p_out_w^T) * gate  (unchanged, fp32)
// ---------------------------------------------------------------------------
__global__ __launch_bounds__(256) void k3_out(
    const float* __restrict__ now, const float* __restrict__ nob,
    const float* __restrict__ poww, float* __restrict__ out)
{
    extern __shared__ float sm[];
    float* Ws = sm;             // [c][d] 128x132
    float* ts = Ws + 128*132;   // [c][j] 128x36
    const int tid = threadIdx.x;
    const int i = blockIdx.y, j0 = blockIdx.x*32;

    for (int idx = tid; idx < 128*128; idx += 256) {
        int d = idx >> 7, c = idx & 127;
        Ws[c*132 + d] = poww[idx];
    }
    for (int idx = tid; idx < 128*32; idx += 256) {
        int c = idx >> 5, j = idx & 31;
        ts[c*36 + j] = g_tri[(size_t)c*PP + (size_t)i*Nn + j0 + j];
    }
    __syncthreads();

    {
        int jl = tid >> 3, sub = tid & 7;
        float s = 0.f, sq = 0.f;
        #pragma unroll
        for (int t = 0; t < 16; ++t) {
            float v = ts[(sub + 8*t)*36 + jl];
            s += v; sq += v*v;
        }
        s  += __shfl_xor_sync(0xffffffffu, s, 1);
        s  += __shfl_xor_sync(0xffffffffu, s, 2);
        s  += __shfl_xor_sync(0xffffffffu, s, 4);
        sq += __shfl_xor_sync(0xffffffffu, sq, 1);
        sq += __shfl_xor_sync(0xffffffffu, sq, 2);
        sq += __shfl_xor_sync(0xffffffffu, sq, 4);
        float mu   = s*(1.f/128.f);
        float rstd = rsqrtf(fmaxf(sq*(1.f/128.f) - mu*mu, 0.f) + 1e-5f);
        #pragma unroll
        for (int t = 0; t < 16; ++t) {
            int c = sub + 8*t;
            ts[c*36 + jl] = (ts[c*36 + jl] - mu)*rstd*now[c] + nob[c];
        }
    }
    __syncthreads();

    const int tx = tid & 31, ty = tid >> 5;
    float acc[4][4] = {};
    #pragma unroll 8
    for (int c = 0; c < 128; ++c) {
        float4 L  = *(const float4*)&ts[c*36 + 4*ty];
        float4 W4 = *(const float4*)&Ws[c*132 + 4*tx];
        float la[4] = {L.x,L.y,L.z,L.w};
        float wa[4] = {W4.x,W4.y,W4.z,W4.w};
        #pragma unroll
        for (int v = 0; v < 4; ++v)
            #pragma unroll
            for (int u = 0; u < 4; ++u)
                acc[v][u] += la[v]*wa[u];
    }
    #pragma unroll
    for (int v = 0; v < 4; ++v) {
        size_t p   = (size_t)i*Nn + j0 + 4*ty + v;
        size_t off = p*Cc + 4*tx;
        float4 g4 = *(const float4*)&g_gate[off];
        float4 o = { acc[v][0]*g4.x, acc[v][1]*g4.y,
                     acc[v][2]*g4.z, acc[v][3]*g4.w };
        *(float4*)&out[off] = o;
    }
}

// ---------------------------------------------------------------------------
extern "C" void kernel_launch(void* const* d_in, const int* in_sizes, int n_in,
                              void* d_out, int out_size)
{
    const float* x    = (const float*)d_in[0];
    const float* niw  = (const float*)d_in[1];
    const float* nib  = (const float*)d_in[2];
    const float* giw  = (const float*)d_in[3];
    const float* piw  = (const float*)d_in[4];
    const float* gow  = (const float*)d_in[5];
    const float* now  = (const float*)d_in[6];
    const float* nob  = (const float*)d_in[7];
    const float* poww = (const float*)d_in[8];
    float* out = (float*)d_out;

    const int k1_smem = (128*XS + 2*64*XS) * 4;       // 135168 B
    const int k2_smem = 4 * K2_BUF * 4;               //  73728 B
    const int k3_smem = (128*132 + 128*36) * 4;       //  86016 B
    cudaFuncSetAttribute(k1_ln_proj,   cudaFuncAttributeMaxDynamicSharedMemorySize, k1_smem);
    cudaFuncSetAttribute(k2_trimul_tc, cudaFuncAttributeMaxDynamicSharedMemorySize, k2_smem);
    cudaFuncSetAttribute(k3_out,       cudaFuncAttributeMaxDynamicSharedMemorySize, k3_smem);

    k1_ln_proj<<<PP/128, 256, k1_smem>>>(x, niw, nib, giw, piw, gow);
    k2_trimul_tc<<<dim3(4, 4, 128), 256, k2_smem>>>();
    k3_out<<<dim3(Nn/32, Nn), 256, k3_smem>>>(now, nob, poww, out);
}

// round 7
// speedup vs baseline: 1.9248x; 1.1572x over previous
#include <cuda_runtime.h>
#include <cstdint>

#define Nn 512
#define Cc 128
#define PP (Nn*Nn)   // 262144 positions

// Scratch (device globals — no allocation allowed in kernel_launch)
__device__ float g_a[(size_t)Cc*PP];     // [c][i][k]  tf32-rounded A operand
__device__ float g_b[(size_t)Cc*PP];     // [c][j][k]  tf32-rounded B operand
__device__ float g_gate[(size_t)PP*Cc];  // [p][c]     sigmoid output gate
__device__ float g_tri[(size_t)Cc*PP];   // [c][i][j]  triangle result

__device__ __forceinline__ float sigmoidf_(float v) {
    return 1.f / (1.f + __expf(-v));
}

// ===================== mma.sync tf32 helpers (sm_80+) ======================
__device__ __forceinline__ uint32_t smem_u32(const void* p) {
    uint32_t a;
    asm("{ .reg .u64 t; cvta.to.shared.u64 t, %1; cvt.u32.u64 %0, t; }"
        : "=r"(a) : "l"(p));
    return a;
}
__device__ __forceinline__ uint32_t cvt_tf32(float f) {
    uint32_t r;
    asm("cvt.rna.tf32.f32 %0, %1;" : "=r"(r) : "f"(f));
    return r;
}
__device__ __forceinline__ void split_tf32(float f, uint32_t& hi, uint32_t& lo) {
    hi = cvt_tf32(f);
    lo = cvt_tf32(f - __uint_as_float(hi));
}
__device__ __forceinline__ void mma_tf32(float* d, const uint32_t* a, const uint32_t* b) {
    asm volatile(
        "mma.sync.aligned.m16n8k8.row.col.f32.tf32.tf32.f32 "
        "{%0,%1,%2,%3}, {%4,%5,%6,%7}, {%8,%9}, {%0,%1,%2,%3};"
        : "+f"(d[0]), "+f"(d[1]), "+f"(d[2]), "+f"(d[3])
        : "r"(a[0]), "r"(a[1]), "r"(a[2]), "r"(a[3]), "r"(b[0]), "r"(b[1]));
}
__device__ __forceinline__ void cp16(uint32_t s, const void* g) {
    asm volatile("cp.async.cg.shared.global [%0], [%1], 16;" :: "r"(s), "l"(g));
}
#define CP_COMMIT() asm volatile("cp.async.commit_group;" ::: "memory")
#define CP_WAIT0()  asm volatile("cp.async.wait_group 0;" ::: "memory")

// ---------------------------------------------------------------------------
// K1: LN + 3 projections via tf32 mma with 3-term precision split (R4-proven).
// Only change vs R4: a/b stores are pre-rounded to tf32 (K2 skips cvt).
// ---------------------------------------------------------------------------
#define XS 132

__global__ __launch_bounds__(256) void k1_ln_proj(
    const float* __restrict__ x,
    const float* __restrict__ niw, const float* __restrict__ nib,
    const float* __restrict__ giw, const float* __restrict__ piw,
    const float* __restrict__ gow)
{
    extern __shared__ float sm[];
    float* xn = sm;            // [128][132]
    float* Wg = xn + 128*XS;   // [64][132]  (also reused as pg staging)
    float* Wp = Wg + 64*XS;    // [64][132]

    const int tid  = threadIdx.x;
    const int p0   = blockIdx.x * 128;
    const int lane = tid & 31, wid = tid >> 5;
    const int wm = wid & 3, wn = wid >> 2;
    const int g4 = lane >> 2, t4 = lane & 3;

    {
        int pos = tid >> 1, sub = tid & 1;
        const float* xr = x + (size_t)(p0 + pos) * Cc + sub * 64;
        float4 bufv[16];
        float s = 0.f, sq = 0.f;
        #pragma unroll
        for (int t = 0; t < 16; ++t) {
            bufv[t] = ((const float4*)xr)[t];
            s  += bufv[t].x + bufv[t].y + bufv[t].z + bufv[t].w;
            sq += bufv[t].x*bufv[t].x + bufv[t].y*bufv[t].y
                + bufv[t].z*bufv[t].z + bufv[t].w*bufv[t].w;
        }
        s  += __shfl_xor_sync(0xffffffffu, s, 1);
        sq += __shfl_xor_sync(0xffffffffu, sq, 1);
        float mu   = s * (1.f/128.f);
        float rstd = rsqrtf(sq * (1.f/128.f) - mu*mu + 1e-5f);
        #pragma unroll
        for (int t = 0; t < 16; ++t) {
            int cb = sub*64 + t*4;
            float4 w4 = *(const float4*)(niw + cb);
            float4 b4 = *(const float4*)(nib + cb);
            float4 o;
            o.x = (bufv[t].x - mu)*rstd*w4.x + b4.x;
            o.y = (bufv[t].y - mu)*rstd*w4.y + b4.y;
            o.z = (bufv[t].z - mu)*rstd*w4.z + b4.z;
            o.w = (bufv[t].w - mu)*rstd*w4.w + b4.w;
            *(float4*)&xn[pos*XS + cb] = o;
        }
    }
    __syncthreads();

    for (int t = 0; t < 4; ++t) {
        const float* gsrc = giw + (size_t)t*64*Cc;
        const float* psrc = piw + (size_t)t*64*Cc;
        for (int q = tid; q < 2048; q += 256) {          // 64 rows x 32 float4
            int d = q >> 5, c4 = q & 31;
            *(float4*)&Wg[d*XS + c4*4] = *(const float4*)(gsrc + d*Cc + c4*4);
            *(float4*)&Wp[d*XS + c4*4] = *(const float4*)(psrc + d*Cc + c4*4);
        }
        __syncthreads();

        float accG[2][4][4] = {}, accP[2][4][4] = {};
        #pragma unroll 4
        for (int ks = 0; ks < 16; ++ks) {
            int kb = ks*8;
            uint32_t ah[2][4], al[2][4];
            #pragma unroll
            for (int mt = 0; mt < 2; ++mt) {
                int row = wm*32 + mt*16 + g4;
                split_tf32(xn[row*XS + kb + t4],         ah[mt][0], al[mt][0]);
                split_tf32(xn[(row+8)*XS + kb + t4],     ah[mt][1], al[mt][1]);
                split_tf32(xn[row*XS + kb + t4 + 4],     ah[mt][2], al[mt][2]);
                split_tf32(xn[(row+8)*XS + kb + t4 + 4], ah[mt][3], al[mt][3]);
            }
            uint32_t bgh[4][2], bgl[4][2], bph[4][2], bpl[4][2];
            #pragma unroll
            for (int nt = 0; nt < 4; ++nt) {
                int dn = wn*32 + nt*8 + g4;
                split_tf32(Wg[dn*XS + kb + t4],     bgh[nt][0], bgl[nt][0]);
                split_tf32(Wg[dn*XS + kb + t4 + 4], bgh[nt][1], bgl[nt][1]);
                split_tf32(Wp[dn*XS + kb + t4],     bph[nt][0], bpl[nt][0]);
                split_tf32(Wp[dn*XS + kb + t4 + 4], bph[nt][1], bpl[nt][1]);
            }
            #pragma unroll
            for (int mt = 0; mt < 2; ++mt)
                #pragma unroll
                for (int nt = 0; nt < 4; ++nt) {
                    mma_tf32(accG[mt][nt], ah[mt], bgh[nt]);
                    mma_tf32(accG[mt][nt], ah[mt], bgl[nt]);
                    mma_tf32(accG[mt][nt], al[mt], bgh[nt]);
                    mma_tf32(accP[mt][nt], ah[mt], bph[nt]);
                    mma_tf32(accP[mt][nt], ah[mt], bpl[nt]);
                    mma_tf32(accP[mt][nt], al[mt], bph[nt]);
                }
        }
        __syncthreads();

        // pg = P * sigmoid(G), stage transposed [d][pos] into Wg
        float* ob = Wg;
        #pragma unroll
        for (int mt = 0; mt < 2; ++mt)
            #pragma unroll
            for (int nt = 0; nt < 4; ++nt) {
                int row = wm*32 + mt*16 + g4;
                int col = wn*32 + nt*8 + 2*t4;
                ob[col*XS + row]         = accP[mt][nt][0]*sigmoidf_(accG[mt][nt][0]);
                ob[(col+1)*XS + row]     = accP[mt][nt][1]*sigmoidf_(accG[mt][nt][1]);
                ob[col*XS + row + 8]     = accP[mt][nt][2]*sigmoidf_(accG[mt][nt][2]);
                ob[(col+1)*XS + row + 8] = accP[mt][nt][3]*sigmoidf_(accG[mt][nt][3]);
            }
        __syncthreads();

        float* dst = ((t < 2) ? g_a : g_b) + (size_t)((t & 1)*64)*PP + p0;
        for (int q = tid; q < 2048; q += 256) {          // 64 d x 32 f4
            int d = q >> 5, p4 = q & 31;
            float4 v = *(float4*)&ob[d*XS + p4*4];
            v.x = __uint_as_float(cvt_tf32(v.x));
            v.y = __uint_as_float(cvt_tf32(v.y));
            v.z = __uint_as_float(cvt_tf32(v.z));
            v.w = __uint_as_float(cvt_tf32(v.w));
            *(float4*)(dst + (size_t)d*PP + p4*4) = v;
        }
        __syncthreads();
    }

    for (int t = 0; t < 2; ++t) {
        const float* gsrc = gow + (size_t)t*64*Cc;
        for (int q = tid; q < 2048; q += 256) {
            int d = q >> 5, c4 = q & 31;
            *(float4*)&Wg[d*XS + c4*4] = *(const float4*)(gsrc + d*Cc + c4*4);
        }
        __syncthreads();

        float accG[2][4][4] = {};
        #pragma unroll 4
        for (int ks = 0; ks < 16; ++ks) {
            int kb = ks*8;
            uint32_t af[2][4];
            #pragma unroll
            for (int mt = 0; mt < 2; ++mt) {
                int row = wm*32 + mt*16 + g4;
                af[mt][0] = cvt_tf32(xn[row*XS + kb + t4]);
                af[mt][1] = cvt_tf32(xn[(row+8)*XS + kb + t4]);
                af[mt][2] = cvt_tf32(xn[row*XS + kb + t4 + 4]);
                af[mt][3] = cvt_tf32(xn[(row+8)*XS + kb + t4 + 4]);
            }
            uint32_t bf[4][2];
            #pragma unroll
            for (int nt = 0; nt < 4; ++nt) {
                int dn = wn*32 + nt*8 + g4;
                bf[nt][0] = cvt_tf32(Wg[dn*XS + kb + t4]);
                bf[nt][1] = cvt_tf32(Wg[dn*XS + kb + t4 + 4]);
            }
            #pragma unroll
            for (int mt = 0; mt < 2; ++mt)
                #pragma unroll
                for (int nt = 0; nt < 4; ++nt)
                    mma_tf32(accG[mt][nt], af[mt], bf[nt]);
        }
        #pragma unroll
        for (int mt = 0; mt < 2; ++mt)
            #pragma unroll
            for (int nt = 0; nt < 4; ++nt) {
                int row = wm*32 + mt*16 + g4;
                int col = t*64 + wn*32 + nt*8 + 2*t4;
                float2 o0 = { sigmoidf_(accG[mt][nt][0]), sigmoidf_(accG[mt][nt][1]) };
                float2 o1 = { sigmoidf_(accG[mt][nt][2]), sigmoidf_(accG[mt][nt][3]) };
                *(float2*)(g_gate + (size_t)(p0+row)*Cc + col)   = o0;
                *(float2*)(g_gate + (size_t)(p0+row+8)*Cc + col) = o1;
            }
        __syncthreads();
    }
}

// ---------------------------------------------------------------------------
// K2: per-channel tri_c = A_c @ B_c^T. Operands are pre-rounded tf32 bits,
// so fragment loads are raw reinterpret (no cvt in the mainloop).
// ---------------------------------------------------------------------------
#define KS2 36
#define K2_BUF (128*KS2)

__global__ __launch_bounds__(256) void k2_trimul_tc()
{
    extern __shared__ float sm2[];
    float* As = sm2;               // [2][128][36]
    float* Bs = sm2 + 2*K2_BUF;    // [2][128][36]

    const int tid = threadIdx.x, lane = tid & 31, wid = tid >> 5;
    const int wm = wid & 3, wn = wid >> 2;
    const int g4 = lane >> 2, t4 = lane & 3;
    const int c = blockIdx.z, i0 = blockIdx.y*128, j0 = blockIdx.x*128;
    const float* Ag = g_a + (size_t)c*PP + (size_t)i0*Nn;
    const float* Bg = g_b + (size_t)c*PP + (size_t)j0*Nn;
    const uint32_t sA = smem_u32(As), sB = smem_u32(Bs);

    const int r_ld  = tid >> 3;
    const int c4_ld = tid & 7;

    float acc[2][8][4] = {};

    #pragma unroll
    for (int q = 0; q < 4; ++q) {
        int r = r_ld + q*32;
        cp16(sA + (uint32_t)(r*KS2 + c4_ld*4)*4, Ag + (size_t)r*Nn + c4_ld*4);
        cp16(sB + (uint32_t)(r*KS2 + c4_ld*4)*4, Bg + (size_t)r*Nn + c4_ld*4);
    }
    CP_COMMIT();

    for (int kt = 0; kt < 16; ++kt) {
        const int buf = kt & 1;
        CP_WAIT0();
        __syncthreads();
        if (kt < 15) {
            const int kk = (kt+1)*32;
            const uint32_t off = (uint32_t)((buf^1)*K2_BUF)*4;
            #pragma unroll
            for (int q = 0; q < 4; ++q) {
                int r = r_ld + q*32;
                cp16(sA + off + (uint32_t)(r*KS2 + c4_ld*4)*4, Ag + (size_t)r*Nn + kk + c4_ld*4);
                cp16(sB + off + (uint32_t)(r*KS2 + c4_ld*4)*4, Bg + (size_t)r*Nn + kk + c4_ld*4);
            }
            CP_COMMIT();
        }
        const float* A = As + buf*K2_BUF;
        const float* B = Bs + buf*K2_BUF;
        #pragma unroll
        for (int ks = 0; ks < 4; ++ks) {
            int kb = ks*8;
            uint32_t af[2][4];
            #pragma unroll
            for (int mt = 0; mt < 2; ++mt) {
                int row = wm*32 + mt*16 + g4;
                af[mt][0] = __float_as_uint(A[row*KS2 + kb + t4]);
                af[mt][1] = __float_as_uint(A[(row+8)*KS2 + kb + t4]);
                af[mt][2] = __float_as_uint(A[row*KS2 + kb + t4 + 4]);
                af[mt][3] = __float_as_uint(A[(row+8)*KS2 + kb + t4 + 4]);
            }
            uint32_t bf[8][2];
            #pragma unroll
            for (int nt = 0; nt < 8; ++nt) {
                int nr = wn*64 + nt*8 + g4;
                bf[nt][0] = __float_as_uint(B[nr*KS2 + kb + t4]);
                bf[nt][1] = __float_as_uint(B[nr*KS2 + kb + t4 + 4]);
            }
            #pragma unroll
            for (int mt = 0; mt < 2; ++mt)
                #pragma unroll
                for (int nt = 0; nt < 8; ++nt)
                    mma_tf32(acc[mt][nt], af[mt], bf[nt]);
        }
        __syncthreads();
    }

    float* Cm = g_tri + (size_t)c*PP;
    #pragma unroll
    for (int mt = 0; mt < 2; ++mt)
        #pragma unroll
        for (int nt = 0; nt < 8; ++nt) {
            int row = i0 + wm*32 + mt*16 + g4;
            int col = j0 + wn*64 + nt*8 + 2*t4;
            float2 o0 = { acc[mt][nt][0], acc[mt][nt][1] };
            float2 o1 = { acc[mt][nt][2], acc[mt][nt][3] };
            *(float2*)(Cm + (size_t)row*Nn + col)     = o0;
            *(float2*)(Cm + (size_t)(row+8)*Nn + col) = o1;
        }
}

// ---------------------------------------------------------------------------
// K3: out = (LN_c(tri) @ p_out_w^T) * gate via tf32 3-term mma.
// ts [c][j] tile, LN in place, A read transposed from ts. grid (4, 512).
// ---------------------------------------------------------------------------
__global__ __launch_bounds__(256) void k3_out(
    const float* __restrict__ now, const float* __restrict__ nob,
    const float* __restrict__ poww, float* __restrict__ out)
{
    extern __shared__ float sm3[];
    float* ts = sm3;            // [128 c][132 j]
    float* Ws = ts + 128*XS;    // [128 d][132 k]

    const int tid  = threadIdx.x;
    const int lane = tid & 31, wid = tid >> 5;
    const int wm = wid & 3, wn = wid >> 2;
    const int g4 = lane >> 2, t4 = lane & 3;
    const int i = blockIdx.y, jb = blockIdx.x;

    for (int q = tid; q < 4096; q += 256) {              // 128 d x 32 f4
        int d = q >> 5, c4 = q & 31;
        *(float4*)&Ws[d*XS + c4*4] = *(const float4*)(poww + (size_t)d*Cc + c4*4);
    }
    const float* tsrc = g_tri + (size_t)i*Nn + jb*128;
    for (int q = tid; q < 4096; q += 256) {              // 128 c x 32 f4
        int c = q >> 5, j4 = q & 31;
        *(float4*)&ts[c*XS + j4*4] = *(const float4*)(tsrc + (size_t)c*PP + j4*4);
    }
    __syncthreads();

    // LN over c, in place (2 threads per j column)
    {
        int j = tid >> 1, sub = tid & 1;
        float s = 0.f, sq = 0.f;
        #pragma unroll 8
        for (int t = 0; t < 64; ++t) {
            float v = ts[(sub*64 + t)*XS + j];
            s += v; sq += v*v;
        }
        s  += __shfl_xor_sync(0xffffffffu, s, 1);
        sq += __shfl_xor_sync(0xffffffffu, sq, 1);
        float mu   = s*(1.f/128.f);
        float rstd = rsqrtf(fmaxf(sq*(1.f/128.f) - mu*mu, 0.f) + 1e-5f);
        #pragma unroll 8
        for (int t = 0; t < 64; ++t) {
            int c = sub*64 + t;
            ts[c*XS + j] = (ts[c*XS + j] - mu)*rstd*now[c] + nob[c];
        }
    }
    __syncthreads();

    float acc[2][8][4] = {};
    #pragma unroll 2
    for (int ks = 0; ks < 16; ++ks) {
        int kb = ks*8;
        uint32_t ah[2][4], al[2][4];
        #pragma unroll
        for (int mt = 0; mt < 2; ++mt) {
            int row = wm*32 + mt*16 + g4;     // j index (M dim)
            split_tf32(ts[(kb + t4)*XS + row],       ah[mt][0], al[mt][0]);
            split_tf32(ts[(kb + t4)*XS + row + 8],   ah[mt][1], al[mt][1]);
            split_tf32(ts[(kb + t4 + 4)*XS + row],   ah[mt][2], al[mt][2]);
            split_tf32(ts[(kb + t4 + 4)*XS + row+8], ah[mt][3], al[mt][3]);
        }
        uint32_t bh[8][2], bl[8][2];
        #pragma unroll
        for (int nt = 0; nt < 8; ++nt) {
            int dn = wn*64 + nt*8 + g4;       // d index (N dim)
            split_tf32(Ws[dn*XS + kb + t4],     bh[nt][0], bl[nt][0]);
            split_tf32(Ws[dn*XS + kb + t4 + 4], bh[nt][1], bl[nt][1]);
        }
        #pragma unroll
        for (int mt = 0; mt < 2; ++mt)
            #pragma unroll
            for (int nt = 0; nt < 8; ++nt) {
                mma_tf32(acc[mt][nt], ah[mt], bh[nt]);
                mma_tf32(acc[mt][nt], ah[mt], bl[nt]);
                mma_tf32(acc[mt][nt], al[mt], bh[nt]);
            }
    }

    const size_t pbase = (size_t)i*Nn + jb*128;
    #pragma unroll
    for (int mt = 0; mt < 2; ++mt)
        #pragma unroll
        for (int nt = 0; nt < 8; ++nt) {
            int row = wm*32 + mt*16 + g4;
            int col = wn*64 + nt*8 + 2*t4;
            size_t off0 = (pbase + row)*Cc + col;
            size_t off1 = (pbase + row + 8)*Cc + col;
            float2 ga = *(const float2*)(g_gate + off0);
            float2 gb = *(const float2*)(g_gate + off1);
            float2 o0 = { acc[mt][nt][0]*ga.x, acc[mt][nt][1]*ga.y };
            float2 o1 = { acc[mt][nt][2]*gb.x, acc[mt][nt][3]*gb.y };
            *(float2*)(out + off0) = o0;
            *(float2*)(out + off1) = o1;
        }
}

// ---------------------------------------------------------------------------
extern "C" void kernel_launch(void* const* d_in, const int* in_sizes, int n_in,
                              void* d_out, int out_size)
{
    const float* x    = (const float*)d_in[0];
    const float* niw  = (const float*)d_in[1];
    const float* nib  = (const float*)d_in[2];
    const float* giw  = (const float*)d_in[3];
    const float* piw  = (const float*)d_in[4];
    const float* gow  = (const float*)d_in[5];
    const float* now  = (const float*)d_in[6];
    const float* nob  = (const float*)d_in[7];
    const float* poww = (const float*)d_in[8];
    float* out = (float*)d_out;

    const int k1_smem = (128*XS + 2*64*XS) * 4;       // 135168 B
    const int k2_smem = 4 * K2_BUF * 4;               //  73728 B
    const int k3_smem = 2 * 128 * XS * 4;             // 135168 B
    cudaFuncSetAttribute(k1_ln_proj,   cudaFuncAttributeMaxDynamicSharedMemorySize, k1_smem);
    cudaFuncSetAttribute(k2_trimul_tc, cudaFuncAttributeMaxDynamicSharedMemorySize, k2_smem);
    cudaFuncSetAttribute(k3_out,       cudaFuncAttributeMaxDynamicSharedMemorySize, k3_smem);

    k1_ln_proj<<<PP/128, 256, k1_smem>>>(x, niw, nib, giw, piw, gow);
    k2_trimul_tc<<<dim3(4, 4, 128), 256, k2_smem>>>();
    k3_out<<<dim3(4, Nn), 256, k3_smem>>>(now, nob, poww, out);
}

// round 8
// speedup vs baseline: 2.1238x; 1.1034x over previous
#include <cuda_runtime.h>
#include <cstdint>

#define Nn 512
#define Cc 128
#define PP (Nn*Nn)   // 262144 positions

// Scratch (device globals — no allocation allowed in kernel_launch)
__device__ float g_a[(size_t)Cc*PP];     // [c][i][k]  tf32-rounded A operand
__device__ float g_b[(size_t)Cc*PP];     // [c][j][k]  tf32-rounded B operand
__device__ float g_gate[(size_t)PP*Cc];  // [p][c]     sigmoid output gate
__device__ float g_tri[(size_t)Cc*PP];   // [c][i][j]  triangle result

__device__ __forceinline__ float sigmoidf_(float v) {
    return 1.f / (1.f + __expf(-v));
}

// ===================== mma.sync tf32 helpers (sm_80+) ======================
__device__ __forceinline__ uint32_t smem_u32(const void* p) {
    uint32_t a;
    asm("{ .reg .u64 t; cvta.to.shared.u64 t, %1; cvt.u32.u64 %0, t; }"
        : "=r"(a) : "l"(p));
    return a;
}
__device__ __forceinline__ uint32_t cvt_tf32(float f) {
    uint32_t r;
    asm("cvt.rna.tf32.f32 %0, %1;" : "=r"(r) : "f"(f));
    return r;
}
__device__ __forceinline__ void split_tf32(float f, uint32_t& hi, uint32_t& lo) {
    hi = cvt_tf32(f);
    lo = cvt_tf32(f - __uint_as_float(hi));
}
__device__ __forceinline__ void mma_tf32(float* d, const uint32_t* a, const uint32_t* b) {
    asm volatile(
        "mma.sync.aligned.m16n8k8.row.col.f32.tf32.tf32.f32 "
        "{%0,%1,%2,%3}, {%4,%5,%6,%7}, {%8,%9}, {%0,%1,%2,%3};"
        : "+f"(d[0]), "+f"(d[1]), "+f"(d[2]), "+f"(d[3])
        : "r"(a[0]), "r"(a[1]), "r"(a[2]), "r"(a[3]), "r"(b[0]), "r"(b[1]));
}
__device__ __forceinline__ void cp16(uint32_t s, const void* g) {
    asm volatile("cp.async.cg.shared.global [%0], [%1], 16;" :: "r"(s), "l"(g));
}
#define CP_COMMIT() asm volatile("cp.async.commit_group;" ::: "memory")
#define CP_WAIT0()  asm volatile("cp.async.wait_group 0;" ::: "memory")

#define XS 132

// ---------------------------------------------------------------------------
// K1 v2: LN + 3 projections. xn pre-split (hi/lo) once into smem; weights
// 1-term tf32 rounded at tile load. Mainloop = pure LDS + HMMA.
// Block = 128 positions, 256 threads (4 pos-warps x 2 d-warps), d-tile 64.
// ---------------------------------------------------------------------------
__global__ __launch_bounds__(256) void k1_ln_proj(
    const float* __restrict__ x,
    const float* __restrict__ niw, const float* __restrict__ nib,
    const float* __restrict__ giw, const float* __restrict__ piw,
    const float* __restrict__ gow)
{
    extern __shared__ char smraw[];
    uint32_t* xnhi = (uint32_t*)smraw;        // [128][132]
    uint32_t* xnlo = xnhi + 128*XS;           // [128][132]
    float*    Wg   = (float*)(xnlo + 128*XS); // [64][132]
    float*    Wp   = Wg + 64*XS;              // [64][132]
    float*    ob   = Wg;                      // staging overlay [64][132]

    const int tid  = threadIdx.x;
    const int p0   = blockIdx.x * 128;
    const int lane = tid & 31, wid = tid >> 5;
    const int wm = wid & 3, wn = wid >> 2;
    const int g4 = lane >> 2, t4 = lane & 3;

    // ---- LayerNorm + tf32 split-pack: 2 threads/position, 64 ch each ----
    {
        int pos = tid >> 1, sub = tid & 1;
        const float* xr = x + (size_t)(p0 + pos) * Cc + sub * 64;
        float4 bufv[16];
        float s = 0.f, sq = 0.f;
        #pragma unroll
        for (int t = 0; t < 16; ++t) {
            bufv[t] = ((const float4*)xr)[t];
            s  += bufv[t].x + bufv[t].y + bufv[t].z + bufv[t].w;
            sq += bufv[t].x*bufv[t].x + bufv[t].y*bufv[t].y
                + bufv[t].z*bufv[t].z + bufv[t].w*bufv[t].w;
        }
        s  += __shfl_xor_sync(0xffffffffu, s, 1);
        sq += __shfl_xor_sync(0xffffffffu, sq, 1);
        float mu   = s * (1.f/128.f);
        float rstd = rsqrtf(sq * (1.f/128.f) - mu*mu + 1e-5f);
        #pragma unroll
        for (int t = 0; t < 16; ++t) {
            int cb = sub*64 + t*4;
            float4 w4 = *(const float4*)(niw + cb);
            float4 b4 = *(const float4*)(nib + cb);
            float o0 = (bufv[t].x - mu)*rstd*w4.x + b4.x;
            float o1 = (bufv[t].y - mu)*rstd*w4.y + b4.y;
            float o2 = (bufv[t].z - mu)*rstd*w4.z + b4.z;
            float o3 = (bufv[t].w - mu)*rstd*w4.w + b4.w;
            uint4 h, l;
            split_tf32(o0, h.x, l.x);
            split_tf32(o1, h.y, l.y);
            split_tf32(o2, h.z, l.z);
            split_tf32(o3, h.w, l.w);
            *(uint4*)&xnhi[pos*XS + cb] = h;
            *(uint4*)&xnlo[pos*XS + cb] = l;
        }
    }
    __syncthreads();

    // ---- 4 dual d-tiles of 64: G = xn@g^T, P = xn@p^T, pg = P*sigmoid(G) ----
    for (int t = 0; t < 4; ++t) {
        const float* gsrc = giw + (size_t)t*64*Cc;
        const float* psrc = piw + (size_t)t*64*Cc;
        for (int q = tid; q < 2048; q += 256) {          // 64 rows x 32 float4
            int d = q >> 5, c4 = q & 31;
            float4 vg = *(const float4*)(gsrc + d*Cc + c4*4);
            float4 vp = *(const float4*)(psrc + d*Cc + c4*4);
            vg.x = __uint_as_float(cvt_tf32(vg.x)); vg.y = __uint_as_float(cvt_tf32(vg.y));
            vg.z = __uint_as_float(cvt_tf32(vg.z)); vg.w = __uint_as_float(cvt_tf32(vg.w));
            vp.x = __uint_as_float(cvt_tf32(vp.x)); vp.y = __uint_as_float(cvt_tf32(vp.y));
            vp.z = __uint_as_float(cvt_tf32(vp.z)); vp.w = __uint_as_float(cvt_tf32(vp.w));
            *(float4*)&Wg[d*XS + c4*4] = vg;
            *(float4*)&Wp[d*XS + c4*4] = vp;
        }
        __syncthreads();

        float accG[2][4][4] = {}, accP[2][4][4] = {};
        #pragma unroll 4
        for (int ks = 0; ks < 16; ++ks) {
            int kb = ks*8;
            uint32_t ah[2][4], al[2][4];
            #pragma unroll
            for (int mt = 0; mt < 2; ++mt) {
                int row = wm*32 + mt*16 + g4;
                ah[mt][0] = xnhi[row*XS + kb + t4];
                ah[mt][1] = xnhi[(row+8)*XS + kb + t4];
                ah[mt][2] = xnhi[row*XS + kb + t4 + 4];
                ah[mt][3] = xnhi[(row+8)*XS + kb + t4 + 4];
                al[mt][0] = xnlo[row*XS + kb + t4];
                al[mt][1] = xnlo[(row+8)*XS + kb + t4];
                al[mt][2] = xnlo[row*XS + kb + t4 + 4];
                al[mt][3] = xnlo[(row+8)*XS + kb + t4 + 4];
            }
            uint32_t bg[4][2], bp[4][2];
            #pragma unroll
            for (int nt = 0; nt < 4; ++nt) {
                int dn = wn*32 + nt*8 + g4;
                bg[nt][0] = __float_as_uint(Wg[dn*XS + kb + t4]);
                bg[nt][1] = __float_as_uint(Wg[dn*XS + kb + t4 + 4]);
                bp[nt][0] = __float_as_uint(Wp[dn*XS + kb + t4]);
                bp[nt][1] = __float_as_uint(Wp[dn*XS + kb + t4 + 4]);
            }
            #pragma unroll
            for (int mt = 0; mt < 2; ++mt)
                #pragma unroll
                for (int nt = 0; nt < 4; ++nt) {
                    mma_tf32(accG[mt][nt], ah[mt], bg[nt]);
                    mma_tf32(accP[mt][nt], ah[mt], bp[nt]);
                    mma_tf32(accG[mt][nt], al[mt], bg[nt]);
                    mma_tf32(accP[mt][nt], al[mt], bp[nt]);
                }
        }
        __syncthreads();

        // pg = P * sigmoid(G), stage transposed [d][pos] (overlay on Wg)
        #pragma unroll
        for (int mt = 0; mt < 2; ++mt)
            #pragma unroll
            for (int nt = 0; nt < 4; ++nt) {
                int row = wm*32 + mt*16 + g4;
                int col = wn*32 + nt*8 + 2*t4;
                ob[col*XS + row]         = accP[mt][nt][0]*sigmoidf_(accG[mt][nt][0]);
                ob[(col+1)*XS + row]     = accP[mt][nt][1]*sigmoidf_(accG[mt][nt][1]);
                ob[col*XS + row + 8]     = accP[mt][nt][2]*sigmoidf_(accG[mt][nt][2]);
                ob[(col+1)*XS + row + 8] = accP[mt][nt][3]*sigmoidf_(accG[mt][nt][3]);
            }
        __syncthreads();

        float* dst = ((t < 2) ? g_a : g_b) + (size_t)((t & 1)*64)*PP + p0;
        for (int q = tid; q < 2048; q += 256) {          // 64 d x 32 f4
            int d = q >> 5, p4 = q & 31;
            float4 v = *(float4*)&ob[d*XS + p4*4];
            v.x = __uint_as_float(cvt_tf32(v.x));
            v.y = __uint_as_float(cvt_tf32(v.y));
            v.z = __uint_as_float(cvt_tf32(v.z));
            v.w = __uint_as_float(cvt_tf32(v.w));
            *(float4*)(dst + (size_t)d*PP + p4*4) = v;
        }
        __syncthreads();
    }

    // ---- 2 gate tiles: gate = sigmoid(xn@g_out^T), 2-term ----
    for (int t = 0; t < 2; ++t) {
        const float* gsrc = gow + (size_t)t*64*Cc;
        for (int q = tid; q < 2048; q += 256) {
            int d = q >> 5, c4 = q & 31;
            float4 vg = *(const float4*)(gsrc + d*Cc + c4*4);
            vg.x = __uint_as_float(cvt_tf32(vg.x)); vg.y = __uint_as_float(cvt_tf32(vg.y));
            vg.z = __uint_as_float(cvt_tf32(vg.z)); vg.w = __uint_as_float(cvt_tf32(vg.w));
            *(float4*)&Wg[d*XS + c4*4] = vg;
        }
        __syncthreads();

        float accG[2][4][4] = {};
        #pragma unroll 4
        for (int ks = 0; ks < 16; ++ks) {
            int kb = ks*8;
            uint32_t ah[2][4], al[2][4];
            #pragma unroll
            for (int mt = 0; mt < 2; ++mt) {
                int row = wm*32 + mt*16 + g4;
                ah[mt][0] = xnhi[row*XS + kb + t4];
                ah[mt][1] = xnhi[(row+8)*XS + kb + t4];
                ah[mt][2] = xnhi[row*XS + kb + t4 + 4];
                ah[mt][3] = xnhi[(row+8)*XS + kb + t4 + 4];
                al[mt][0] = xnlo[row*XS + kb + t4];
                al[mt][1] = xnlo[(row+8)*XS + kb + t4];
                al[mt][2] = xnlo[row*XS + kb + t4 + 4];
                al[mt][3] = xnlo[(row+8)*XS + kb + t4 + 4];
            }
            uint32_t bf[4][2];
            #pragma unroll
            for (int nt = 0; nt < 4; ++nt) {
                int dn = wn*32 + nt*8 + g4;
                bf[nt][0] = __float_as_uint(Wg[dn*XS + kb + t4]);
                bf[nt][1] = __float_as_uint(Wg[dn*XS + kb + t4 + 4]);
            }
            #pragma unroll
            for (int mt = 0; mt < 2; ++mt)
                #pragma unroll
                for (int nt = 0; nt < 4; ++nt) {
                    mma_tf32(accG[mt][nt], ah[mt], bf[nt]);
                    mma_tf32(accG[mt][nt], al[mt], bf[nt]);
                }
        }
        #pragma unroll
        for (int mt = 0; mt < 2; ++mt)
            #pragma unroll
            for (int nt = 0; nt < 4; ++nt) {
                int row = wm*32 + mt*16 + g4;
                int col = t*64 + wn*32 + nt*8 + 2*t4;
                float2 o0 = { sigmoidf_(accG[mt][nt][0]), sigmoidf_(accG[mt][nt][1]) };
                float2 o1 = { sigmoidf_(accG[mt][nt][2]), sigmoidf_(accG[mt][nt][3]) };
                *(float2*)(g_gate + (size_t)(p0+row)*Cc + col)   = o0;
                *(float2*)(g_gate + (size_t)(p0+row+8)*Cc + col) = o1;
            }
        __syncthreads();
    }
}

// ---------------------------------------------------------------------------
// K2: per-channel tri_c = A_c @ B_c^T (unchanged from R7).
// ---------------------------------------------------------------------------
#define KS2 36
#define K2_BUF (128*KS2)

__global__ __launch_bounds__(256) void k2_trimul_tc()
{
    extern __shared__ float sm2[];
    float* As = sm2;               // [2][128][36]
    float* Bs = sm2 + 2*K2_BUF;    // [2][128][36]

    const int tid = threadIdx.x, lane = tid & 31, wid = tid >> 5;
    const int wm = wid & 3, wn = wid >> 2;
    const int g4 = lane >> 2, t4 = lane & 3;
    const int c = blockIdx.z, i0 = blockIdx.y*128, j0 = blockIdx.x*128;
    const float* Ag = g_a + (size_t)c*PP + (size_t)i0*Nn;
    const float* Bg = g_b + (size_t)c*PP + (size_t)j0*Nn;
    const uint32_t sA = smem_u32(As), sB = smem_u32(Bs);

    const int r_ld  = tid >> 3;
    const int c4_ld = tid & 7;

    float acc[2][8][4] = {};

    #pragma unroll
    for (int q = 0; q < 4; ++q) {
        int r = r_ld + q*32;
        cp16(sA + (uint32_t)(r*KS2 + c4_ld*4)*4, Ag + (size_t)r*Nn + c4_ld*4);
        cp16(sB + (uint32_t)(r*KS2 + c4_ld*4)*4, Bg + (size_t)r*Nn + c4_ld*4);
    }
    CP_COMMIT();

    for (int kt = 0; kt < 16; ++kt) {
        const int buf = kt & 1;
        CP_WAIT0();
        __syncthreads();
        if (kt < 15) {
            const int kk = (kt+1)*32;
            const uint32_t off = (uint32_t)((buf^1)*K2_BUF)*4;
            #pragma unroll
            for (int q = 0; q < 4; ++q) {
                int r = r_ld + q*32;
                cp16(sA + off + (uint32_t)(r*KS2 + c4_ld*4)*4, Ag + (size_t)r*Nn + kk + c4_ld*4);
                cp16(sB + off + (uint32_t)(r*KS2 + c4_ld*4)*4, Bg + (size_t)r*Nn + kk + c4_ld*4);
            }
            CP_COMMIT();
        }
        const float* A = As + buf*K2_BUF;
        const float* B = Bs + buf*K2_BUF;
        #pragma unroll
        for (int ks = 0; ks < 4; ++ks) {
            int kb = ks*8;
            uint32_t af[2][4];
            #pragma unroll
            for (int mt = 0; mt < 2; ++mt) {
                int row = wm*32 + mt*16 + g4;
                af[mt][0] = __float_as_uint(A[row*KS2 + kb + t4]);
                af[mt][1] = __float_as_uint(A[(row+8)*KS2 + kb + t4]);
                af[mt][2] = __float_as_uint(A[row*KS2 + kb + t4 + 4]);
                af[mt][3] = __float_as_uint(A[(row+8)*KS2 + kb + t4 + 4]);
            }
            uint32_t bf[8][2];
            #pragma unroll
            for (int nt = 0; nt < 8; ++nt) {
                int nr = wn*64 + nt*8 + g4;
                bf[nt][0] = __float_as_uint(B[nr*KS2 + kb + t4]);
                bf[nt][1] = __float_as_uint(B[nr*KS2 + kb + t4 + 4]);
            }
            #pragma unroll
            for (int mt = 0; mt < 2; ++mt)
                #pragma unroll
                for (int nt = 0; nt < 8; ++nt)
                    mma_tf32(acc[mt][nt], af[mt], bf[nt]);
        }
        __syncthreads();
    }

    float* Cm = g_tri + (size_t)c*PP;
    #pragma unroll
    for (int mt = 0; mt < 2; ++mt)
        #pragma unroll
        for (int nt = 0; nt < 8; ++nt) {
            int row = i0 + wm*32 + mt*16 + g4;
            int col = j0 + wn*64 + nt*8 + 2*t4;
            float2 o0 = { acc[mt][nt][0], acc[mt][nt][1] };
            float2 o1 = { acc[mt][nt][2], acc[mt][nt][3] };
            *(float2*)(Cm + (size_t)row*Nn + col)     = o0;
            *(float2*)(Cm + (size_t)(row+8)*Nn + col) = o1;
        }
}

// ---------------------------------------------------------------------------
// K3: out = (LN_c(tri) @ p_out_w^T) * gate via tf32 3-term mma (unchanged).
// ---------------------------------------------------------------------------
__global__ __launch_bounds__(256) void k3_out(
    const float* __restrict__ now, const float* __restrict__ nob,
    const float* __restrict__ poww, float* __restrict__ out)
{
    extern __shared__ float sm3[];
    float* ts = sm3;            // [128 c][132 j]
    float* Ws = ts + 128*XS;    // [128 d][132 k]

    const int tid  = threadIdx.x;
    const int lane = tid & 31, wid = tid >> 5;
    const int wm = wid & 3, wn = wid >> 2;
    const int g4 = lane >> 2, t4 = lane & 3;
    const int i = blockIdx.y, jb = blockIdx.x;

    for (int q = tid; q < 4096; q += 256) {
        int d = q >> 5, c4 = q & 31;
        *(float4*)&Ws[d*XS + c4*4] = *(const float4*)(poww + (size_t)d*Cc + c4*4);
    }
    const float* tsrc = g_tri + (size_t)i*Nn + jb*128;
    for (int q = tid; q < 4096; q += 256) {
        int c = q >> 5, j4 = q & 31;
        *(float4*)&ts[c*XS + j4*4] = *(const float4*)(tsrc + (size_t)c*PP + j4*4);
    }
    __syncthreads();

    {
        int j = tid >> 1, sub = tid & 1;
        float s = 0.f, sq = 0.f;
        #pragma unroll 8
        for (int t = 0; t < 64; ++t) {
            float v = ts[(sub*64 + t)*XS + j];
            s += v; sq += v*v;
        }
        s  += __shfl_xor_sync(0xffffffffu, s, 1);
        sq += __shfl_xor_sync(0xffffffffu, sq, 1);
        float mu   = s*(1.f/128.f);
        float rstd = rsqrtf(fmaxf(sq*(1.f/128.f) - mu*mu, 0.f) + 1e-5f);
        #pragma unroll 8
        for (int t = 0; t < 64; ++t) {
            int c = sub*64 + t;
            ts[c*XS + j] = (ts[c*XS + j] - mu)*rstd*now[c] + nob[c];
        }
    }
    __syncthreads();

    float acc[2][8][4] = {};
    #pragma unroll 2
    for (int ks = 0; ks < 16; ++ks) {
        int kb = ks*8;
        uint32_t ah[2][4], al[2][4];
        #pragma unroll
        for (int mt = 0; mt < 2; ++mt) {
            int row = wm*32 + mt*16 + g4;
            split_tf32(ts[(kb + t4)*XS + row],       ah[mt][0], al[mt][0]);
            split_tf32(ts[(kb + t4)*XS + row + 8],   ah[mt][1], al[mt][1]);
            split_tf32(ts[(kb + t4 + 4)*XS + row],   ah[mt][2], al[mt][2]);
            split_tf32(ts[(kb + t4 + 4)*XS + row+8], ah[mt][3], al[mt][3]);
        }
        uint32_t bh[8][2], bl[8][2];
        #pragma unroll
        for (int nt = 0; nt < 8; ++nt) {
            int dn = wn*64 + nt*8 + g4;
            split_tf32(Ws[dn*XS + kb + t4],     bh[nt][0], bl[nt][0]);
            split_tf32(Ws[dn*XS + kb + t4 + 4], bh[nt][1], bl[nt][1]);
        }
        #pragma unroll
        for (int mt = 0; mt < 2; ++mt)
            #pragma unroll
            for (int nt = 0; nt < 8; ++nt) {
                mma_tf32(acc[mt][nt], ah[mt], bh[nt]);
                mma_tf32(acc[mt][nt], ah[mt], bl[nt]);
                mma_tf32(acc[mt][nt], al[mt], bh[nt]);
            }
    }

    const size_t pbase = (size_t)i*Nn + jb*128;
    #pragma unroll
    for (int mt = 0; mt < 2; ++mt)
        #pragma unroll
        for (int nt = 0; nt < 8; ++nt) {
            int row = wm*32 + mt*16 + g4;
            int col = wn*64 + nt*8 + 2*t4;
            size_t off0 = (pbase + row)*Cc + col;
            size_t off1 = (pbase + row + 8)*Cc + col;
            float2 ga = *(const float2*)(g_gate + off0);
            float2 gb = *(const float2*)(g_gate + off1);
            float2 o0 = { acc[mt][nt][0]*ga.x, acc[mt][nt][1]*ga.y };
            float2 o1 = { acc[mt][nt][2]*gb.x, acc[mt][nt][3]*gb.y };
            *(float2*)(out + off0) = o0;
            *(float2*)(out + off1) = o1;
        }
}

// ---------------------------------------------------------------------------
extern "C" void kernel_launch(void* const* d_in, const int* in_sizes, int n_in,
                              void* d_out, int out_size)
{
    const float* x    = (const float*)d_in[0];
    const float* niw  = (const float*)d_in[1];
    const float* nib  = (const float*)d_in[2];
    const float* giw  = (const float*)d_in[3];
    const float* piw  = (const float*)d_in[4];
    const float* gow  = (const float*)d_in[5];
    const float* now  = (const float*)d_in[6];
    const float* nob  = (const float*)d_in[7];
    const float* poww = (const float*)d_in[8];
    float* out = (float*)d_out;

    const int k1_smem = (2*128*XS + 2*64*XS) * 4;     // 202752 B
    const int k2_smem = 4 * K2_BUF * 4;               //  73728 B
    const int k3_smem = 2 * 128 * XS * 4;             // 135168 B
    cudaFuncSetAttribute(k1_ln_proj,   cudaFuncAttributeMaxDynamicSharedMemorySize, k1_smem);
    cudaFuncSetAttribute(k2_trimul_tc, cudaFuncAttributeMaxDynamicSharedMemorySize, k2_smem);
    cudaFuncSetAttribute(k3_out,       cudaFuncAttributeMaxDynamicSharedMemorySize, k3_smem);

    k1_ln_proj<<<PP/128, 256, k1_smem>>>(x, niw, nib, giw, piw, gow);
    k2_trimul_tc<<<dim3(4, 4, 128), 256, k2_smem>>>();
    k3_out<<<dim3(4, Nn), 256, k3_smem>>>(now, nob, poww, out);
}

// round 9
// speedup vs baseline: 2.7711x; 1.3047x over previous
#include <cuda_runtime.h>
#include <cstdint>

#define Nn 512
#define Cc 128
#define PP (Nn*Nn)   // 262144 positions

// Scratch (device globals — no allocation allowed in kernel_launch)
__device__ float g_a[(size_t)Cc*PP];     // [c][i][k]  tf32-rounded A operand
__device__ float g_b[(size_t)Cc*PP];     // [c][j][k]  tf32-rounded B operand
__device__ float g_gate[(size_t)PP*Cc];  // [p][c]     sigmoid output gate
__device__ float g_tri[(size_t)Cc*PP];   // [c][i][j]  triangle result

__device__ __forceinline__ float sigmoidf_(float v) {
    return 1.f / (1.f + __expf(-v));
}

// ===================== mma.sync tf32 helpers (sm_80+) ======================
__device__ __forceinline__ uint32_t smem_u32(const void* p) {
    uint32_t a;
    asm("{ .reg .u64 t; cvta.to.shared.u64 t, %1; cvt.u32.u64 %0, t; }"
        : "=r"(a) : "l"(p));
    return a;
}
__device__ __forceinline__ uint32_t cvt_tf32(float f) {
    uint32_t r;
    asm("cvt.rna.tf32.f32 %0, %1;" : "=r"(r) : "f"(f));
    return r;
}
__device__ __forceinline__ float round_tf32(float f) {
    return __uint_as_float(cvt_tf32(f));
}
__device__ __forceinline__ void split_tf32(float f, uint32_t& hi, uint32_t& lo) {
    hi = cvt_tf32(f);
    lo = cvt_tf32(f - __uint_as_float(hi));
}
__device__ __forceinline__ void mma_tf32(float* d, const uint32_t* a, const uint32_t* b) {
    asm volatile(
        "mma.sync.aligned.m16n8k8.row.col.f32.tf32.tf32.f32 "
        "{%0,%1,%2,%3}, {%4,%5,%6,%7}, {%8,%9}, {%0,%1,%2,%3};"
        : "+f"(d[0]), "+f"(d[1]), "+f"(d[2]), "+f"(d[3])
        : "r"(a[0]), "r"(a[1]), "r"(a[2]), "r"(a[3]), "r"(b[0]), "r"(b[1]));
}
__device__ __forceinline__ void cp16(uint32_t s, const void* g) {
    asm volatile("cp.async.cg.shared.global [%0], [%1], 16;" :: "r"(s), "l"(g));
}
#define CP_COMMIT() asm volatile("cp.async.commit_group;" ::: "memory")
#define CP_WAIT0()  asm volatile("cp.async.wait_group 0;" ::: "memory")

#define XS 132

// ---------------------------------------------------------------------------
// K1 v3: LN + 3 projections, 1-term tf32, 2 CTAs/SM.
// xn tf32-rounded in LN phase; weights rounded at tile load; d-tile 32.
// Block = 128 positions, 256 threads (4 pos-warps x 2 d-warps).
// smem = 128*132*4 + 2*32*132*4 = 101376 B -> 2 CTAs/SM.
// ---------------------------------------------------------------------------
__global__ __launch_bounds__(256, 2) void k1_ln_proj(
    const float* __restrict__ x,
    const float* __restrict__ niw, const float* __restrict__ nib,
    const float* __restrict__ giw, const float* __restrict__ piw,
    const float* __restrict__ gow)
{
    extern __shared__ float sm[];
    float* xn = sm;              // [128][132] tf32-rounded LN output
    float* Wg = xn + 128*XS;     // [32][132]
    float* Wp = Wg + 32*XS;      // [32][132]
    float* ob = Wg;              // staging overlay [32][132]

    const int tid  = threadIdx.x;
    const int p0   = blockIdx.x * 128;
    const int lane = tid & 31, wid = tid >> 5;
    const int wm = wid & 3, wn = wid >> 2;   // pos-warp (32 rows), d-warp (16 cols)
    const int g4 = lane >> 2, t4 = lane & 3;

    // ---- LayerNorm (+ tf32 rounding): 2 threads/position, 64 ch each ----
    {
        int pos = tid >> 1, sub = tid & 1;
        const float* xr = x + (size_t)(p0 + pos) * Cc + sub * 64;
        float4 bufv[16];
        float s = 0.f, sq = 0.f;
        #pragma unroll
        for (int t = 0; t < 16; ++t) {
            bufv[t] = ((const float4*)xr)[t];
            s  += bufv[t].x + bufv[t].y + bufv[t].z + bufv[t].w;
            sq += bufv[t].x*bufv[t].x + bufv[t].y*bufv[t].y
                + bufv[t].z*bufv[t].z + bufv[t].w*bufv[t].w;
        }
        s  += __shfl_xor_sync(0xffffffffu, s, 1);
        sq += __shfl_xor_sync(0xffffffffu, sq, 1);
        float mu   = s * (1.f/128.f);
        float rstd = rsqrtf(sq * (1.f/128.f) - mu*mu + 1e-5f);
        #pragma unroll
        for (int t = 0; t < 16; ++t) {
            int cb = sub*64 + t*4;
            float4 w4 = *(const float4*)(niw + cb);
            float4 b4 = *(const float4*)(nib + cb);
            float4 o;
            o.x = round_tf32((bufv[t].x - mu)*rstd*w4.x + b4.x);
            o.y = round_tf32((bufv[t].y - mu)*rstd*w4.y + b4.y);
            o.z = round_tf32((bufv[t].z - mu)*rstd*w4.z + b4.z);
            o.w = round_tf32((bufv[t].w - mu)*rstd*w4.w + b4.w);
            *(float4*)&xn[pos*XS + cb] = o;
        }
    }
    __syncthreads();

    // ---- 8 dual d-tiles of 32: G = xn@g^T, P = xn@p^T, pg = P*sigmoid(G) ----
    for (int t = 0; t < 8; ++t) {
        const float* gsrc = giw + (size_t)t*32*Cc;
        const float* psrc = piw + (size_t)t*32*Cc;
        for (int q = tid; q < 1024; q += 256) {          // 32 rows x 32 float4
            int d = q >> 5, c4 = q & 31;
            float4 vg = *(const float4*)(gsrc + d*Cc + c4*4);
            float4 vp = *(const float4*)(psrc + d*Cc + c4*4);
            vg.x = round_tf32(vg.x); vg.y = round_tf32(vg.y);
            vg.z = round_tf32(vg.z); vg.w = round_tf32(vg.w);
            vp.x = round_tf32(vp.x); vp.y = round_tf32(vp.y);
            vp.z = round_tf32(vp.z); vp.w = round_tf32(vp.w);
            *(float4*)&Wg[d*XS + c4*4] = vg;
            *(float4*)&Wp[d*XS + c4*4] = vp;
        }
        __syncthreads();

        float accG[2][2][4] = {}, accP[2][2][4] = {};
        #pragma unroll 4
        for (int ks = 0; ks < 16; ++ks) {
            int kb = ks*8;
            uint32_t af[2][4];
            #pragma unroll
            for (int mt = 0; mt < 2; ++mt) {
                int row = wm*32 + mt*16 + g4;
                af[mt][0] = __float_as_uint(xn[row*XS + kb + t4]);
                af[mt][1] = __float_as_uint(xn[(row+8)*XS + kb + t4]);
                af[mt][2] = __float_as_uint(xn[row*XS + kb + t4 + 4]);
                af[mt][3] = __float_as_uint(xn[(row+8)*XS + kb + t4 + 4]);
            }
            uint32_t bg[2][2], bp[2][2];
            #pragma unroll
            for (int nt = 0; nt < 2; ++nt) {
                int dn = wn*16 + nt*8 + g4;
                bg[nt][0] = __float_as_uint(Wg[dn*XS + kb + t4]);
                bg[nt][1] = __float_as_uint(Wg[dn*XS + kb + t4 + 4]);
                bp[nt][0] = __float_as_uint(Wp[dn*XS + kb + t4]);
                bp[nt][1] = __float_as_uint(Wp[dn*XS + kb + t4 + 4]);
            }
            #pragma unroll
            for (int mt = 0; mt < 2; ++mt)
                #pragma unroll
                for (int nt = 0; nt < 2; ++nt) {
                    mma_tf32(accG[mt][nt], af[mt], bg[nt]);
                    mma_tf32(accP[mt][nt], af[mt], bp[nt]);
                }
        }
        __syncthreads();

        // pg = P * sigmoid(G), stage transposed [d][pos] (overlay on Wg)
        #pragma unroll
        for (int mt = 0; mt < 2; ++mt)
            #pragma unroll
            for (int nt = 0; nt < 2; ++nt) {
                int row = wm*32 + mt*16 + g4;
                int col = wn*16 + nt*8 + 2*t4;
                ob[col*XS + row]         = accP[mt][nt][0]*sigmoidf_(accG[mt][nt][0]);
                ob[(col+1)*XS + row]     = accP[mt][nt][1]*sigmoidf_(accG[mt][nt][1]);
                ob[col*XS + row + 8]     = accP[mt][nt][2]*sigmoidf_(accG[mt][nt][2]);
                ob[(col+1)*XS + row + 8] = accP[mt][nt][3]*sigmoidf_(accG[mt][nt][3]);
            }
        __syncthreads();

        float* dst = ((t < 4) ? g_a : g_b) + (size_t)((t & 3)*32)*PP + p0;
        for (int q = tid; q < 1024; q += 256) {          // 32 d x 32 f4
            int d = q >> 5, p4 = q & 31;
            float4 v = *(float4*)&ob[d*XS + p4*4];
            v.x = round_tf32(v.x); v.y = round_tf32(v.y);
            v.z = round_tf32(v.z); v.w = round_tf32(v.w);
            *(float4*)(dst + (size_t)d*PP + p4*4) = v;
        }
        __syncthreads();
    }

    // ---- 4 gate tiles of 32: gate = sigmoid(xn@g_out^T), 1-term ----
    for (int t = 0; t < 4; ++t) {
        const float* gsrc = gow + (size_t)t*32*Cc;
        for (int q = tid; q < 1024; q += 256) {
            int d = q >> 5, c4 = q & 31;
            float4 vg = *(const float4*)(gsrc + d*Cc + c4*4);
            vg.x = round_tf32(vg.x); vg.y = round_tf32(vg.y);
            vg.z = round_tf32(vg.z); vg.w = round_tf32(vg.w);
            *(float4*)&Wg[d*XS + c4*4] = vg;
        }
        __syncthreads();

        float accG[2][2][4] = {};
        #pragma unroll 4
        for (int ks = 0; ks < 16; ++ks) {
            int kb = ks*8;
            uint32_t af[2][4];
            #pragma unroll
            for (int mt = 0; mt < 2; ++mt) {
                int row = wm*32 + mt*16 + g4;
                af[mt][0] = __float_as_uint(xn[row*XS + kb + t4]);
                af[mt][1] = __float_as_uint(xn[(row+8)*XS + kb + t4]);
                af[mt][2] = __float_as_uint(xn[row*XS + kb + t4 + 4]);
                af[mt][3] = __float_as_uint(xn[(row+8)*XS + kb + t4 + 4]);
            }
            uint32_t bf[2][2];
            #pragma unroll
            for (int nt = 0; nt < 2; ++nt) {
                int dn = wn*16 + nt*8 + g4;
                bf[nt][0] = __float_as_uint(Wg[dn*XS + kb + t4]);
                bf[nt][1] = __float_as_uint(Wg[dn*XS + kb + t4 + 4]);
            }
            #pragma unroll
            for (int mt = 0; mt < 2; ++mt)
                #pragma unroll
                for (int nt = 0; nt < 2; ++nt)
                    mma_tf32(accG[mt][nt], af[mt], bf[nt]);
        }
        #pragma unroll
        for (int mt = 0; mt < 2; ++mt)
            #pragma unroll
            for (int nt = 0; nt < 2; ++nt) {
                int row = wm*32 + mt*16 + g4;
                int col = t*32 + wn*16 + nt*8 + 2*t4;
                float2 o0 = { sigmoidf_(accG[mt][nt][0]), sigmoidf_(accG[mt][nt][1]) };
                float2 o1 = { sigmoidf_(accG[mt][nt][2]), sigmoidf_(accG[mt][nt][3]) };
                *(float2*)(g_gate + (size_t)(p0+row)*Cc + col)   = o0;
                *(float2*)(g_gate + (size_t)(p0+row+8)*Cc + col) = o1;
            }
        __syncthreads();
    }
}

// ---------------------------------------------------------------------------
// K2: per-channel tri_c = A_c @ B_c^T (unchanged from R7/R8).
// ---------------------------------------------------------------------------
#define KS2 36
#define K2_BUF (128*KS2)

__global__ __launch_bounds__(256) void k2_trimul_tc()
{
    extern __shared__ float sm2[];
    float* As = sm2;               // [2][128][36]
    float* Bs = sm2 + 2*K2_BUF;    // [2][128][36]

    const int tid = threadIdx.x, lane = tid & 31, wid = tid >> 5;
    const int wm = wid & 3, wn = wid >> 2;
    const int g4 = lane >> 2, t4 = lane & 3;
    const int c = blockIdx.z, i0 = blockIdx.y*128, j0 = blockIdx.x*128;
    const float* Ag = g_a + (size_t)c*PP + (size_t)i0*Nn;
    const float* Bg = g_b + (size_t)c*PP + (size_t)j0*Nn;
    const uint32_t sA = smem_u32(As), sB = smem_u32(Bs);

    const int r_ld  = tid >> 3;
    const int c4_ld = tid & 7;

    float acc[2][8][4] = {};

    #pragma unroll
    for (int q = 0; q < 4; ++q) {
        int r = r_ld + q*32;
        cp16(sA + (uint32_t)(r*KS2 + c4_ld*4)*4, Ag + (size_t)r*Nn + c4_ld*4);
        cp16(sB + (uint32_t)(r*KS2 + c4_ld*4)*4, Bg + (size_t)r*Nn + c4_ld*4);
    }
    CP_COMMIT();

    for (int kt = 0; kt < 16; ++kt) {
        const int buf = kt & 1;
        CP_WAIT0();
        __syncthreads();
        if (kt < 15) {
            const int kk = (kt+1)*32;
            const uint32_t off = (uint32_t)((buf^1)*K2_BUF)*4;
            #pragma unroll
            for (int q = 0; q < 4; ++q) {
                int r = r_ld + q*32;
                cp16(sA + off + (uint32_t)(r*KS2 + c4_ld*4)*4, Ag + (size_t)r*Nn + kk + c4_ld*4);
                cp16(sB + off + (uint32_t)(r*KS2 + c4_ld*4)*4, Bg + (size_t)r*Nn + kk + c4_ld*4);
            }
            CP_COMMIT();
        }
        const float* A = As + buf*K2_BUF;
        const float* B = Bs + buf*K2_BUF;
        #pragma unroll
        for (int ks = 0; ks < 4; ++ks) {
            int kb = ks*8;
            uint32_t af[2][4];
            #pragma unroll
            for (int mt = 0; mt < 2; ++mt) {
                int row = wm*32 + mt*16 + g4;
                af[mt][0] = __float_as_uint(A[row*KS2 + kb + t4]);
                af[mt][1] = __float_as_uint(A[(row+8)*KS2 + kb + t4]);
                af[mt][2] = __float_as_uint(A[row*KS2 + kb + t4 + 4]);
                af[mt][3] = __float_as_uint(A[(row+8)*KS2 + kb + t4 + 4]);
            }
            uint32_t bf[8][2];
            #pragma unroll
            for (int nt = 0; nt < 8; ++nt) {
                int nr = wn*64 + nt*8 + g4;
                bf[nt][0] = __float_as_uint(B[nr*KS2 + kb + t4]);
                bf[nt][1] = __float_as_uint(B[nr*KS2 + kb + t4 + 4]);
            }
            #pragma unroll
            for (int mt = 0; mt < 2; ++mt)
                #pragma unroll
                for (int nt = 0; nt < 8; ++nt)
                    mma_tf32(acc[mt][nt], af[mt], bf[nt]);
        }
        __syncthreads();
    }

    float* Cm = g_tri + (size_t)c*PP;
    #pragma unroll
    for (int mt = 0; mt < 2; ++mt)
        #pragma unroll
        for (int nt = 0; nt < 8; ++nt) {
            int row = i0 + wm*32 + mt*16 + g4;
            int col = j0 + wn*64 + nt*8 + 2*t4;
            float2 o0 = { acc[mt][nt][0], acc[mt][nt][1] };
            float2 o1 = { acc[mt][nt][2], acc[mt][nt][3] };
            *(float2*)(Cm + (size_t)row*Nn + col)     = o0;
            *(float2*)(Cm + (size_t)(row+8)*Nn + col) = o1;
        }
}

// ---------------------------------------------------------------------------
// K3: out = (LN_c(tri) @ p_out_w^T) * gate. A 2-term, W 1-term (pre-rounded).
// ---------------------------------------------------------------------------
__global__ __launch_bounds__(256) void k3_out(
    const float* __restrict__ now, const float* __restrict__ nob,
    const float* __restrict__ poww, float* __restrict__ out)
{
    extern __shared__ float sm3[];
    float* ts = sm3;            // [128 c][132 j]
    float* Ws = ts + 128*XS;    // [128 d][132 k] tf32-rounded

    const int tid  = threadIdx.x;
    const int lane = tid & 31, wid = tid >> 5;
    const int wm = wid & 3, wn = wid >> 2;
    const int g4 = lane >> 2, t4 = lane & 3;
    const int i = blockIdx.y, jb = blockIdx.x;

    for (int q = tid; q < 4096; q += 256) {
        int d = q >> 5, c4 = q & 31;
        float4 v = *(const float4*)(poww + (size_t)d*Cc + c4*4);
        v.x = round_tf32(v.x); v.y = round_tf32(v.y);
        v.z = round_tf32(v.z); v.w = round_tf32(v.w);
        *(float4*)&Ws[d*XS + c4*4] = v;
    }
    const float* tsrc = g_tri + (size_t)i*Nn + jb*128;
    for (int q = tid; q < 4096; q += 256) {
        int c = q >> 5, j4 = q & 31;
        *(float4*)&ts[c*XS + j4*4] = *(const float4*)(tsrc + (size_t)c*PP + j4*4);
    }
    __syncthreads();

    {
        int j = tid >> 1, sub = tid & 1;
        float s = 0.f, sq = 0.f;
        #pragma unroll 8
        for (int t = 0; t < 64; ++t) {
            float v = ts[(sub*64 + t)*XS + j];
            s += v; sq += v*v;
        }
        s  += __shfl_xor_sync(0xffffffffu, s, 1);
        sq += __shfl_xor_sync(0xffffffffu, sq, 1);
        float mu   = s*(1.f/128.f);
        float rstd = rsqrtf(fmaxf(sq*(1.f/128.f) - mu*mu, 0.f) + 1e-5f);
        #pragma unroll 8
        for (int t = 0; t < 64; ++t) {
            int c = sub*64 + t;
            ts[c*XS + j] = (ts[c*XS + j] - mu)*rstd*now[c] + nob[c];
        }
    }
    __syncthreads();

    float acc[2][8][4] = {};
    #pragma unroll 2
    for (int ks = 0; ks < 16; ++ks) {
        int kb = ks*8;
        uint32_t ah[2][4], al[2][4];
        #pragma unroll
        for (int mt = 0; mt < 2; ++mt) {
            int row = wm*32 + mt*16 + g4;
            split_tf32(ts[(kb + t4)*XS + row],       ah[mt][0], al[mt][0]);
            split_tf32(ts[(kb + t4)*XS + row + 8],   ah[mt][1], al[mt][1]);
            split_tf32(ts[(kb + t4 + 4)*XS + row],   ah[mt][2], al[mt][2]);
            split_tf32(ts[(kb + t4 + 4)*XS + row+8], ah[mt][3], al[mt][3]);
        }
        uint32_t bh[8][2];
        #pragma unroll
        for (int nt = 0; nt < 8; ++nt) {
            int dn = wn*64 + nt*8 + g4;
            bh[nt][0] = __float_as_uint(Ws[dn*XS + kb + t4]);
            bh[nt][1] = __float_as_uint(Ws[dn*XS + kb + t4 + 4]);
        }
        #pragma unroll
        for (int mt = 0; mt < 2; ++mt)
            #pragma unroll
            for (int nt = 0; nt < 8; ++nt) {
                mma_tf32(acc[mt][nt], ah[mt], bh[nt]);
                mma_tf32(acc[mt][nt], al[mt], bh[nt]);
            }
    }

    const size_t pbase = (size_t)i*Nn + jb*128;
    #pragma unroll
    for (int mt = 0; mt < 2; ++mt)
        #pragma unroll
        for (int nt = 0; nt < 8; ++nt) {
            int row = wm*32 + mt*16 + g4;
            int col = wn*64 + nt*8 + 2*t4;
            size_t off0 = (pbase + row)*Cc + col;
            size_t off1 = (pbase + row + 8)*Cc + col;
            float2 ga = *(const float2*)(g_gate + off0);
            float2 gb = *(const float2*)(g_gate + off1);
            float2 o0 = { acc[mt][nt][0]*ga.x, acc[mt][nt][1]*ga.y };
            float2 o1 = { acc[mt][nt][2]*gb.x, acc[mt][nt][3]*gb.y };
            *(float2*)(out + off0) = o0;
            *(float2*)(out + off1) = o1;
        }
}

// ---------------------------------------------------------------------------
extern "C" void kernel_launch(void* const* d_in, const int* in_sizes, int n_in,
                              void* d_out, int out_size)
{
    const float* x    = (const float*)d_in[0];
    const float* niw  = (const float*)d_in[1];
    const float* nib  = (const float*)d_in[2];
    const float* giw  = (const float*)d_in[3];
    const float* piw  = (const float*)d_in[4];
    const float* gow  = (const float*)d_in[5];
    const float* now  = (const float*)d_in[6];
    const float* nob  = (const float*)d_in[7];
    const float* poww = (const float*)d_in[8];
    float* out = (float*)d_out;

    const int k1_smem = (128*XS + 2*32*XS) * 4;       // 101376 B (2 CTAs/SM)
    const int k2_smem = 4 * K2_BUF * 4;               //  73728 B
    const int k3_smem = 2 * 128 * XS * 4;             // 135168 B
    cudaFuncSetAttribute(k1_ln_proj,   cudaFuncAttributeMaxDynamicSharedMemorySize, k1_smem);
    cudaFuncSetAttribute(k2_trimul_tc, cudaFuncAttributeMaxDynamicSharedMemorySize, k2_smem);
    cudaFuncSetAttribute(k3_out,       cudaFuncAttributeMaxDynamicSharedMemorySize, k3_smem);

    k1_ln_proj<<<PP/128, 256, k1_smem>>>(x, niw, nib, giw, piw, gow);
    k2_trimul_tc<<<dim3(4, 4, 128), 256, k2_smem>>>();
    k3_out<<<dim3(4, Nn), 256, k3_smem>>>(now, nob, poww, out);
}